// round 11
// baseline (speedup 1.0000x reference)
#include <cuda_runtime.h>
#include <cuda_fp16.h>
#include <math.h>

#define D_MODEL 512
#define N_HEADS 8
#define HEAD_DIM 64
#define D_FF 2048
#define SEQ 4096
#define BATCH 2
#define ROWS (BATCH*SEQ)
#define BH (BATCH*N_HEADS)

// scratch buffers (no allocation allowed)
__device__ __half  g_xln_h [ROWS*D_MODEL];
__device__ __half  g_Qh    [BH*SEQ*HEAD_DIM];
__device__ __half  g_Kh    [BH*SEQ*HEAD_DIM];
__device__ __half  g_Vh    [BH*SEQ*HEAD_DIM];
__device__ __half  g_ctx_h [ROWS*D_MODEL];
__device__ float   g_src2  [ROWS*D_MODEL];
__device__ __half  g_hid_h [ROWS*D_FF];
__device__ float2  g_rope  [SEQ*32];
__device__ __half  g_wqkv_h[3*D_MODEL*D_MODEL];
__device__ __half  g_outw_h[D_MODEL*D_MODEL];
__device__ __half  g_ff1_h [D_FF*D_MODEL];
__device__ __half  g_ff2_h [D_MODEL*D_FF];

// asm macros
#define CP16(dst, src) \
    asm volatile("cp.async.cg.shared.global [%0], [%1], 16;" :: "r"(dst), "l"(src))
#define CPCOMMIT() asm volatile("cp.async.commit_group;")
#define CPWAIT0()  asm volatile("cp.async.wait_group 0;")
#define CPWAIT1()  asm volatile("cp.async.wait_group 1;")
#define LDSM4(r0, r1, r2, r3, addr) \
    asm volatile("ldmatrix.sync.aligned.m8n8.x4.shared.b16 {%0,%1,%2,%3}, [%4];" \
                 : "=r"(r0), "=r"(r1), "=r"(r2), "=r"(r3) : "r"(addr))
#define LDSM4T(r0, r1, r2, r3, addr) \
    asm volatile("ldmatrix.sync.aligned.m8n8.x4.trans.shared.b16 {%0,%1,%2,%3}, [%4];" \
                 : "=r"(r0), "=r"(r1), "=r"(r2), "=r"(r3) : "r"(addr))
#define MMA168(c0, c1, c2, c3, a0, a1, a2, a3, b0, b1) \
    asm volatile("mma.sync.aligned.m16n8k16.row.col.f32.f16.f16.f32 " \
                 "{%0,%1,%2,%3},{%4,%5,%6,%7},{%8,%9},{%0,%1,%2,%3};" \
                 : "+f"(c0), "+f"(c1), "+f"(c2), "+f"(c3) \
                 : "r"(a0), "r"(a1), "r"(a2), "r"(a3), "r"(b0), "r"(b1))

__device__ __forceinline__ unsigned smem_u32(const void* p)
{
    return (unsigned)__cvta_generic_to_shared(p);
}
__device__ __forceinline__ unsigned pack_h2(float a, float b)
{
    __half2 h = __floats2half2_rn(a, b);
    return *reinterpret_cast<unsigned*>(&h);
}

// fused fp32 -> fp16 for all four weight tensors
#define N4_QKV (3*D_MODEL*D_MODEL/4)
#define N4_OUT (D_MODEL*D_MODEL/4)
#define N4_FF1 (D_FF*D_MODEL/4)
#define N4_FF2 (D_MODEL*D_FF/4)
__global__ void __launch_bounds__(256) f2h_all(const float* __restrict__ w0,
                                               const float* __restrict__ w1,
                                               const float* __restrict__ w2,
                                               const float* __restrict__ w3,
                                               __half* __restrict__ o0,
                                               __half* __restrict__ o1,
                                               __half* __restrict__ o2,
                                               __half* __restrict__ o3)
{
    int i = blockIdx.x * 256 + threadIdx.x;
    const float* in;
    __half* out;
    int k;
    if (i < N4_QKV) {
        in = w0; out = o0; k = i;
    } else if (i < N4_QKV + N4_OUT) {
        in = w1; out = o1; k = i - N4_QKV;
    } else if (i < N4_QKV + N4_OUT + N4_FF1) {
        in = w2; out = o2; k = i - N4_QKV - N4_OUT;
    } else if (i < N4_QKV + N4_OUT + N4_FF1 + N4_FF2) {
        in = w3; out = o3; k = i - N4_QKV - N4_OUT - N4_FF1;
    } else {
        return;
    }
    float4 v = reinterpret_cast<const float4*>(in)[k];
    reinterpret_cast<__half2*>(out)[k * 2 + 0] = __floats2half2_rn(v.x, v.y);
    reinterpret_cast<__half2*>(out)[k * 2 + 1] = __floats2half2_rn(v.z, v.w);
}

// LayerNorm, one block per row of 512, half output
__global__ void __launch_bounds__(128) ln_kernel(const float* __restrict__ x,
                                                 const float* __restrict__ w,
                                                 const float* __restrict__ b,
                                                 __half* __restrict__ y)
{
    int row = blockIdx.x;
    int t = threadIdx.x;
    const float4* xr = reinterpret_cast<const float4*>(x) + (size_t)row * 128;
    float4 v = xr[t];
    float s  = v.x + v.y + v.z + v.w;
    float ss = v.x*v.x + v.y*v.y + v.z*v.z + v.w*v.w;
    #pragma unroll
    for (int off = 16; off >= 1; off >>= 1) {
        s  += __shfl_xor_sync(0xffffffffu, s,  off);
        ss += __shfl_xor_sync(0xffffffffu, ss, off);
    }
    __shared__ float rs[4], rss[4];
    int wid = t >> 5;
    if ((t & 31) == 0) { rs[wid] = s; rss[wid] = ss; }
    __syncthreads();
    s  = rs[0] + rs[1] + rs[2] + rs[3];
    ss = rss[0] + rss[1] + rss[2] + rss[3];
    float mu  = s * (1.0f / 512.0f);
    float var = ss * (1.0f / 512.0f) - mu * mu;
    float r   = rsqrtf(var + 1e-5f);
    float4 w4 = reinterpret_cast<const float4*>(w)[t];
    float4 b4 = reinterpret_cast<const float4*>(b)[t];
    __half2* yr = reinterpret_cast<__half2*>(y) + (size_t)row * 256;
    yr[t * 2 + 0] = __floats2half2_rn((v.x - mu) * r * w4.x + b4.x,
                                      (v.y - mu) * r * w4.y + b4.y);
    yr[t * 2 + 1] = __floats2half2_rn((v.z - mu) * r * w4.z + b4.z,
                                      (v.w - mu) * r * w4.w + b4.w);
}

// RoPE table
__global__ void __launch_bounds__(256) rope_tab_kernel(float2* __restrict__ tab)
{
    int idx = blockIdx.x * 256 + threadIdx.x;
    int s = idx >> 5;
    int i = idx & 31;
    double freq = 1.0 / pow(10000.0, (double)i / 32.0);
    float ang = (float)((double)s * freq);
    tab[idx] = make_float2(cosf(ang), sinf(ang));
}

// raw mma NT GEMM: C[M,N] = A[M,K] * W[N,K]^T
// 128x128 block tile, BK=64, 3-stage cp.async ring, ldmatrix + XOR swizzle.
// 4 warps in 2x2, warp tile 64x64, register accumulators, direct epilogue.
// OUTM: 0 = fp32 C (+resid), 1 = half Ch, 2 = fused rope split to Q/K/V
#define GSTAGE 16384u
#define GEMM_SMEM (6 * 16384)

template<bool RELU, bool RESID, int OUTM>
__global__ void __launch_bounds__(128) gemm_mma(const __half* __restrict__ A,
                                                const __half* __restrict__ W,
                                                const float* __restrict__ bias,
                                                const float* __restrict__ resid,
                                                float* __restrict__ C,
                                                __half* __restrict__ Ch,
                                                __half* __restrict__ Qp,
                                                __half* __restrict__ Kp,
                                                __half* __restrict__ Vp,
                                                const float2* __restrict__ tab,
                                                int M, int N, int K)
{
    extern __shared__ __half smg[];
    unsigned aA = smem_u32(smg);
    unsigned aB = aA + 3 * GSTAGE;
    int tid = threadIdx.x;
    int lane = tid & 31;
    int wid = tid >> 5;
    int wr = wid >> 1;
    int wc = wid & 1;
    int lr = lane & 7;
    int lg = lane >> 3;
    int bm = blockIdx.y * 128;
    int bn = blockIdx.x * 128;
    int nK = K >> 6;

    const __half* Ag = A + (size_t)bm * K;
    const __half* Wg = W + (size_t)bn * K;

    float acc[4][8][4];
    #pragma unroll
    for (int i = 0; i < 4; i++) {
        #pragma unroll
        for (int j = 0; j < 8; j++) {
            acc[i][j][0] = 0.0f; acc[i][j][1] = 0.0f;
            acc[i][j][2] = 0.0f; acc[i][j][3] = 0.0f;
        }
    }

    // prologue: stages 0 and 1
    for (int st = 0; st < 2; st++) {
        unsigned dA = aA + (unsigned)st * GSTAGE;
        unsigned dB = aB + (unsigned)st * GSTAGE;
        int k0 = st * 64;
        #pragma unroll
        for (int i2 = 0; i2 < 8; i2++) {
            int idx = tid + i2 * 128;
            int rr = idx >> 3;
            int cc = idx & 7;
            CP16(dA + rr * 128 + ((cc ^ (rr & 7)) << 4), Ag + (size_t)rr * K + k0 + cc * 8);
            CP16(dB + rr * 128 + ((cc ^ (rr & 7)) << 4), Wg + (size_t)rr * K + k0 + cc * 8);
        }
        CPCOMMIT();
    }

    for (int kt = 0; kt < nK; kt++) {
        if (kt < nK - 1) {
            CPWAIT1();
        } else {
            CPWAIT0();
        }
        __syncthreads();
        if (kt + 2 < nK) {
            int st = (kt + 2) % 3;
            unsigned dA = aA + (unsigned)st * GSTAGE;
            unsigned dB = aB + (unsigned)st * GSTAGE;
            int k0 = (kt + 2) * 64;
            #pragma unroll
            for (int i2 = 0; i2 < 8; i2++) {
                int idx = tid + i2 * 128;
                int rr = idx >> 3;
                int cc = idx & 7;
                CP16(dA + rr * 128 + ((cc ^ (rr & 7)) << 4), Ag + (size_t)rr * K + k0 + cc * 8);
                CP16(dB + rr * 128 + ((cc ^ (rr & 7)) << 4), Wg + (size_t)rr * K + k0 + cc * 8);
            }
            CPCOMMIT();
        }
        unsigned cA = aA + (unsigned)(kt % 3) * GSTAGE;
        unsigned cB = aB + (unsigned)(kt % 3) * GSTAGE;
        #pragma unroll
        for (int kc = 0; kc < 4; kc++) {
            // A fragments: 4 x 16-row groups of this warp's 64 rows
            unsigned af[4][4];
            int ach = kc * 2 + (lg >> 1);
            #pragma unroll
            for (int i = 0; i < 4; i++) {
                int arow = wr * 64 + i * 16 + ((lg & 1) << 3) + lr;
                LDSM4(af[i][0], af[i][1], af[i][2], af[i][3],
                      cA + arow * 128 + ((ach ^ (arow & 7)) << 4));
            }
            int bch = kc * 2 + (lg & 1);
            #pragma unroll
            for (int jj = 0; jj < 4; jj++) {
                int brow = wc * 64 + jj * 16 + ((lg >> 1) << 3) + lr;
                unsigned b0, b1, b2, b3;
                LDSM4(b0, b1, b2, b3, cB + brow * 128 + ((bch ^ (brow & 7)) << 4));
                #pragma unroll
                for (int i = 0; i < 4; i++) {
                    MMA168(acc[i][2*jj][0], acc[i][2*jj][1], acc[i][2*jj][2], acc[i][2*jj][3],
                           af[i][0], af[i][1], af[i][2], af[i][3], b0, b1);
                    MMA168(acc[i][2*jj+1][0], acc[i][2*jj+1][1], acc[i][2*jj+1][2], acc[i][2*jj+1][3],
                           af[i][0], af[i][1], af[i][2], af[i][3], b2, b3);
                }
            }
        }
    }

    // epilogue straight from registers
    #pragma unroll
    for (int i = 0; i < 4; i++) {
        int r1 = bm + wr * 64 + i * 16 + (lane >> 2);
        int r2 = r1 + 8;
        #pragma unroll
        for (int j = 0; j < 8; j++) {
            int gc = bn + wc * 64 + j * 8 + (lane & 3) * 2;
            float2 bb = *reinterpret_cast<const float2*>(&bias[gc]);
            float c0 = acc[i][j][0] + bb.x;
            float c1 = acc[i][j][1] + bb.y;
            float c2 = acc[i][j][2] + bb.x;
            float c3 = acc[i][j][3] + bb.y;
            if (RELU) {
                c0 = fmaxf(c0, 0.0f); c1 = fmaxf(c1, 0.0f);
                c2 = fmaxf(c2, 0.0f); c3 = fmaxf(c3, 0.0f);
            }
            if (OUTM == 0) {
                if (RESID) {
                    float2 rv1 = *reinterpret_cast<const float2*>(&resid[(size_t)r1 * N + gc]);
                    float2 rv2 = *reinterpret_cast<const float2*>(&resid[(size_t)r2 * N + gc]);
                    c0 += rv1.x; c1 += rv1.y;
                    c2 += rv2.x; c3 += rv2.y;
                }
                *reinterpret_cast<float2*>(&C[(size_t)r1 * N + gc]) = make_float2(c0, c1);
                *reinterpret_cast<float2*>(&C[(size_t)r2 * N + gc]) = make_float2(c2, c3);
            } else if (OUTM == 1) {
                *reinterpret_cast<__half2*>(&Ch[(size_t)r1 * N + gc]) = __floats2half2_rn(c0, c1);
                *reinterpret_cast<__half2*>(&Ch[(size_t)r2 * N + gc]) = __floats2half2_rn(c2, c3);
            } else {
                int type = gc >> 9;
                int head = (gc >> 6) & 7;
                int d    = gc & 63;
                int s1 = r1 & (SEQ - 1);
                int s2 = r2 & (SEQ - 1);
                int bi1 = r1 >> 12;
                int bi2 = r2 >> 12;
                size_t oo1 = ((((size_t)bi1 * 8 + head) * SEQ) + s1) * 64 + d;
                size_t oo2 = ((((size_t)bi2 * 8 + head) * SEQ) + s2) * 64 + d;
                if (type == 2) {
                    *reinterpret_cast<__half2*>(&Vp[oo1]) = __floats2half2_rn(c0, c1);
                    *reinterpret_cast<__half2*>(&Vp[oo2]) = __floats2half2_rn(c2, c3);
                } else {
                    float2 cs1 = tab[s1 * 32 + (d >> 1)];
                    float2 cs2 = tab[s2 * 32 + (d >> 1)];
                    float x1 = c0 * cs1.x - c1 * cs1.y;
                    float y1 = c0 * cs1.y + c1 * cs1.x;
                    float x2 = c2 * cs2.x - c3 * cs2.y;
                    float y2 = c2 * cs2.y + c3 * cs2.x;
                    if (type == 0) {
                        *reinterpret_cast<__half2*>(&Qp[oo1]) =
                            __floats2half2_rn(x1 * 0.125f, y1 * 0.125f);
                        *reinterpret_cast<__half2*>(&Qp[oo2]) =
                            __floats2half2_rn(x2 * 0.125f, y2 * 0.125f);
                    } else {
                        *reinterpret_cast<__half2*>(&Kp[oo1]) = __floats2half2_rn(x1, y1);
                        *reinterpret_cast<__half2*>(&Kp[oo2]) = __floats2half2_rn(x2, y2);
                    }
                }
            }
        }
    }
}

// register-resident causal flash attention (identical to round-6/7/8/10 passing version)
__global__ void __launch_bounds__(128) flash_mma(const __half* __restrict__ Qg,
                                                 const __half* __restrict__ Kg,
                                                 const __half* __restrict__ Vg,
                                                 __half* __restrict__ ctx)
{
    __shared__ __half sQ[4096];
    __shared__ __half sK0[4096];
    __shared__ __half sK1[4096];
    __shared__ __half sV0[4096];
    __shared__ __half sV1[4096];

    int qt = (int)gridDim.x - 1 - blockIdx.x;
    int bh = blockIdx.y;
    int bb = bh >> 3;
    int hh = bh & 7;
    const __half* Qb = Qg + ((size_t)bh * SEQ + qt * 64) * 64;
    const __half* Kb = Kg + (size_t)bh * SEQ * 64;
    const __half* Vb = Vg + (size_t)bh * SEQ * 64;

    int tid = threadIdx.x;
    int lane = tid & 31;
    int wq = tid >> 5;
    int lr = lane & 7;
    int lg = lane >> 3;
    unsigned aQ = smem_u32(sQ);
    unsigned aK0 = smem_u32(sK0);
    unsigned aK1 = smem_u32(sK1);
    unsigned aV0 = smem_u32(sV0);
    unsigned aV1 = smem_u32(sV1);

    {
        int r = tid >> 1;
        int cbase = (tid & 1) * 4;
        #pragma unroll
        for (int c = cbase; c < cbase + 4; c++) {
            CP16(aQ  + r * 128 + ((c ^ (r & 7)) << 4), Qb + r * 64 + c * 8);
            CP16(aK0 + r * 128 + ((c ^ (r & 7)) << 4), Kb + r * 64 + c * 8);
            CP16(aV0 + r * 128 + ((c ^ (r & 7)) << 4), Vb + r * 64 + c * 8);
        }
    }
    CPCOMMIT();
    CPWAIT0();
    __syncthreads();

    unsigned qa[4][4];
    #pragma unroll
    for (int kc = 0; kc < 4; kc++) {
        int qrow = wq * 16 + ((lg & 1) << 3) + lr;
        int qch  = kc * 2 + (lg >> 1);
        LDSM4(qa[kc][0], qa[kc][1], qa[kc][2], qa[kc][3],
              aQ + qrow * 128 + ((qch ^ (qrow & 7)) << 4));
    }

    float O[8][4];
    #pragma unroll
    for (int j = 0; j < 8; j++) {
        O[j][0] = 0.0f; O[j][1] = 0.0f; O[j][2] = 0.0f; O[j][3] = 0.0f;
    }
    float m1 = -1e30f;
    float m2 = -1e30f;
    float l1 = 0.0f;
    float l2 = 0.0f;

    int grow1 = qt * 64 + wq * 16 + (lane >> 2);
    int grow2 = grow1 + 8;

    for (int kt = 0; kt <= qt; ++kt) {
        unsigned curK = (kt & 1) ? aK1 : aK0;
        unsigned curV = (kt & 1) ? aV1 : aV0;
        unsigned nxtK = (kt & 1) ? aK0 : aK1;
        unsigned nxtV = (kt & 1) ? aV0 : aV1;
        if (kt < qt) {
            const __half* Kn = Kb + (size_t)(kt + 1) * 4096;
            const __half* Vn = Vb + (size_t)(kt + 1) * 4096;
            int r = tid >> 1;
            int cbase = (tid & 1) * 4;
            #pragma unroll
            for (int c = cbase; c < cbase + 4; c++) {
                CP16(nxtK + r * 128 + ((c ^ (r & 7)) << 4), Kn + r * 64 + c * 8);
                CP16(nxtV + r * 128 + ((c ^ (r & 7)) << 4), Vn + r * 64 + c * 8);
            }
            CPCOMMIT();
        }

        float S[8][4];
        #pragma unroll
        for (int j = 0; j < 8; j++) {
            S[j][0] = 0.0f; S[j][1] = 0.0f; S[j][2] = 0.0f; S[j][3] = 0.0f;
        }
        #pragma unroll
        for (int ng = 0; ng < 4; ng++) {
            #pragma unroll
            for (int kc = 0; kc < 4; kc++) {
                int krow = ng * 16 + ((lg >> 1) << 3) + lr;
                int kch  = kc * 2 + (lg & 1);
                unsigned b0, b1, b2, b3;
                LDSM4(b0, b1, b2, b3, curK + krow * 128 + ((kch ^ (krow & 7)) << 4));
                MMA168(S[ng * 2][0], S[ng * 2][1], S[ng * 2][2], S[ng * 2][3],
                       qa[kc][0], qa[kc][1], qa[kc][2], qa[kc][3], b0, b1);
                MMA168(S[ng * 2 + 1][0], S[ng * 2 + 1][1], S[ng * 2 + 1][2], S[ng * 2 + 1][3],
                       qa[kc][0], qa[kc][1], qa[kc][2], qa[kc][3], b2, b3);
            }
        }

        if (kt == qt) {
            #pragma unroll
            for (int j = 0; j < 8; j++) {
                int col = kt * 64 + j * 8 + (lane & 3) * 2;
                if (col     > grow1) S[j][0] = -1e30f;
                if (col + 1 > grow1) S[j][1] = -1e30f;
                if (col     > grow2) S[j][2] = -1e30f;
                if (col + 1 > grow2) S[j][3] = -1e30f;
            }
        }

        float mx1 = -1e30f;
        float mx2 = -1e30f;
        #pragma unroll
        for (int j = 0; j < 8; j++) {
            mx1 = fmaxf(mx1, fmaxf(S[j][0], S[j][1]));
            mx2 = fmaxf(mx2, fmaxf(S[j][2], S[j][3]));
        }
        mx1 = fmaxf(mx1, __shfl_xor_sync(0xffffffffu, mx1, 1));
        mx1 = fmaxf(mx1, __shfl_xor_sync(0xffffffffu, mx1, 2));
        mx2 = fmaxf(mx2, __shfl_xor_sync(0xffffffffu, mx2, 1));
        mx2 = fmaxf(mx2, __shfl_xor_sync(0xffffffffu, mx2, 2));
        float mn1 = fmaxf(m1, mx1);
        float mn2 = fmaxf(m2, mx2);
        float al1 = __expf(m1 - mn1);
        float al2 = __expf(m2 - mn2);
        float sm1 = 0.0f;
        float sm2 = 0.0f;
        #pragma unroll
        for (int j = 0; j < 8; j++) {
            S[j][0] = __expf(S[j][0] - mn1);
            S[j][1] = __expf(S[j][1] - mn1);
            S[j][2] = __expf(S[j][2] - mn2);
            S[j][3] = __expf(S[j][3] - mn2);
            sm1 += S[j][0] + S[j][1];
            sm2 += S[j][2] + S[j][3];
        }
        sm1 += __shfl_xor_sync(0xffffffffu, sm1, 1);
        sm1 += __shfl_xor_sync(0xffffffffu, sm1, 2);
        sm2 += __shfl_xor_sync(0xffffffffu, sm2, 1);
        sm2 += __shfl_xor_sync(0xffffffffu, sm2, 2);
        l1 = l1 * al1 + sm1;
        l2 = l2 * al2 + sm2;
        m1 = mn1;
        m2 = mn2;
        #pragma unroll
        for (int j = 0; j < 8; j++) {
            O[j][0] *= al1; O[j][1] *= al1;
            O[j][2] *= al2; O[j][3] *= al2;
        }

        unsigned pa[4][4];
        #pragma unroll
        for (int kc = 0; kc < 4; kc++) {
            pa[kc][0] = pack_h2(S[2 * kc][0],     S[2 * kc][1]);
            pa[kc][1] = pack_h2(S[2 * kc][2],     S[2 * kc][3]);
            pa[kc][2] = pack_h2(S[2 * kc + 1][0], S[2 * kc + 1][1]);
            pa[kc][3] = pack_h2(S[2 * kc + 1][2], S[2 * kc + 1][3]);
        }

        #pragma unroll
        for (int dg = 0; dg < 4; dg++) {
            #pragma unroll
            for (int tc = 0; tc < 4; tc++) {
                int vrow = tc * 16 + ((lg & 1) << 3) + lr;
                int vch  = dg * 2 + (lg >> 1);
                unsigned v0, v1, v2, v3;
                LDSM4T(v0, v1, v2, v3, curV + vrow * 128 + ((vch ^ (vrow & 7)) << 4));
                MMA168(O[dg * 2][0], O[dg * 2][1], O[dg * 2][2], O[dg * 2][3],
                       pa[tc][0], pa[tc][1], pa[tc][2], pa[tc][3], v0, v1);
                MMA168(O[dg * 2 + 1][0], O[dg * 2 + 1][1], O[dg * 2 + 1][2], O[dg * 2 + 1][3],
                       pa[tc][0], pa[tc][1], pa[tc][2], pa[tc][3], v2, v3);
            }
        }

        if (kt < qt) {
            CPWAIT0();
            __syncthreads();
        }
    }

    float inv1 = 1.0f / l1;
    float inv2 = 1.0f / l2;
    size_t base1 = ((size_t)bb * SEQ + grow1) * 512 + hh * 64;
    size_t base2 = ((size_t)bb * SEQ + grow2) * 512 + hh * 64;
    #pragma unroll
    for (int j = 0; j < 8; j++) {
        int col = j * 8 + (lane & 3) * 2;
        *reinterpret_cast<__half2*>(&ctx[base1 + col]) =
            __floats2half2_rn(O[j][0] * inv1, O[j][1] * inv1);
        *reinterpret_cast<__half2*>(&ctx[base2 + col]) =
            __floats2half2_rn(O[j][2] * inv2, O[j][3] * inv2);
    }
}

extern "C" void kernel_launch(void* const* d_in, const int* in_sizes, int n_in,
                              void* d_out, int out_size)
{
    const float* src      = (const float*)d_in[0];
    const float* ln_w     = (const float*)d_in[1];
    const float* ln_b     = (const float*)d_in[2];
    const float* wqkv_w   = (const float*)d_in[3];
    const float* wqkv_b   = (const float*)d_in[4];
    const float* out_w    = (const float*)d_in[5];
    const float* out_b    = (const float*)d_in[6];
    const float* ffn_ln_w = (const float*)d_in[7];
    const float* ffn_ln_b = (const float*)d_in[8];
    const float* ff1_w    = (const float*)d_in[9];
    const float* ff1_b    = (const float*)d_in[10];
    const float* ff2_w    = (const float*)d_in[11];
    const float* ff2_b    = (const float*)d_in[12];
    float* out = (float*)d_out;

    __half *xln, *Q, *K, *V, *ctx, *hid, *wqkvh, *outwh, *ff1h, *ff2h;
    float *src2;
    float2* tab;
    cudaGetSymbolAddress((void**)&xln,   g_xln_h);
    cudaGetSymbolAddress((void**)&Q,     g_Qh);
    cudaGetSymbolAddress((void**)&K,     g_Kh);
    cudaGetSymbolAddress((void**)&V,     g_Vh);
    cudaGetSymbolAddress((void**)&ctx,   g_ctx_h);
    cudaGetSymbolAddress((void**)&src2,  g_src2);
    cudaGetSymbolAddress((void**)&hid,   g_hid_h);
    cudaGetSymbolAddress((void**)&tab,   g_rope);
    cudaGetSymbolAddress((void**)&wqkvh, g_wqkv_h);
    cudaGetSymbolAddress((void**)&outwh, g_outw_h);
    cudaGetSymbolAddress((void**)&ff1h,  g_ff1_h);
    cudaGetSymbolAddress((void**)&ff2h,  g_ff2_h);

    cudaFuncSetAttribute(gemm_mma<false, false, 2>,
                         cudaFuncAttributeMaxDynamicSharedMemorySize, GEMM_SMEM);
    cudaFuncSetAttribute(gemm_mma<false, true, 0>,
                         cudaFuncAttributeMaxDynamicSharedMemorySize, GEMM_SMEM);
    cudaFuncSetAttribute(gemm_mma<true, false, 1>,
                         cudaFuncAttributeMaxDynamicSharedMemorySize, GEMM_SMEM);

    int n4_total = N4_QKV + N4_OUT + N4_FF1 + N4_FF2;
    f2h_all<<<(n4_total + 255) / 256, 256>>>(wqkv_w, out_w, ff1_w, ff2_w,
                                             wqkvh, outwh, ff1h, ff2h);
    rope_tab_kernel<<<(SEQ * 32) / 256, 256>>>(tab);
    ln_kernel<<<ROWS, 128>>>(src, ln_w, ln_b, xln);

    // QKV projection with fused rope + split
    gemm_mma<false, false, 2><<<dim3(12, 64), 128, GEMM_SMEM>>>(
        xln, wqkvh, wqkv_b, nullptr, nullptr, nullptr, Q, K, V, tab,
        ROWS, 3 * D_MODEL, D_MODEL);

    flash_mma<<<dim3(SEQ / 64, BH), 128>>>(Q, K, V, ctx);

    gemm_mma<false, true, 0><<<dim3(4, 64), 128, GEMM_SMEM>>>(
        ctx, outwh, out_b, src, src2, nullptr, nullptr, nullptr, nullptr, nullptr,
        ROWS, D_MODEL, D_MODEL);

    ln_kernel<<<ROWS, 128>>>(src2, ffn_ln_w, ffn_ln_b, xln);

    gemm_mma<true, false, 1><<<dim3(16, 64), 128, GEMM_SMEM>>>(
        xln, ff1h, ff1_b, nullptr, nullptr, hid, nullptr, nullptr, nullptr, nullptr,
        ROWS, D_FF, D_MODEL);

    gemm_mma<false, true, 0><<<dim3(4, 64), 128, GEMM_SMEM>>>(
        hid, ff2h, ff2_b, src2, out, nullptr, nullptr, nullptr, nullptr, nullptr,
        ROWS, D_MODEL, D_FF);
}

// round 13
// speedup vs baseline: 1.0804x; 1.0804x over previous
#include <cuda_runtime.h>
#include <cuda_fp16.h>
#include <math.h>

#define D_MODEL 512
#define N_HEADS 8
#define HEAD_DIM 64
#define D_FF 2048
#define SEQ 4096
#define BATCH 2
#define ROWS (BATCH*SEQ)
#define BH (BATCH*N_HEADS)

// scratch buffers (no allocation allowed)
__device__ __half  g_xln_h [ROWS*D_MODEL];
__device__ __half  g_Qh    [BH*SEQ*HEAD_DIM];
__device__ __half  g_Kh    [BH*SEQ*HEAD_DIM];
__device__ __half  g_Vh    [BH*SEQ*HEAD_DIM];
__device__ __half  g_ctx_h [ROWS*D_MODEL];
__device__ float   g_src2  [ROWS*D_MODEL];
__device__ __half  g_hid_h [ROWS*D_FF];
__device__ float2  g_rope  [SEQ*32];
__device__ __half  g_wqkv_h[3*D_MODEL*D_MODEL];
__device__ __half  g_outw_h[D_MODEL*D_MODEL];
__device__ __half  g_ff1_h [D_FF*D_MODEL];
__device__ __half  g_ff2_h [D_MODEL*D_FF];

// asm macros
#define CP16(dst, src) \
    asm volatile("cp.async.cg.shared.global [%0], [%1], 16;" :: "r"(dst), "l"(src))
#define CPCOMMIT() asm volatile("cp.async.commit_group;")
#define CPWAIT0()  asm volatile("cp.async.wait_group 0;")
#define CPWAIT1()  asm volatile("cp.async.wait_group 1;")
#define LDSM4(r0, r1, r2, r3, addr) \
    asm volatile("ldmatrix.sync.aligned.m8n8.x4.shared.b16 {%0,%1,%2,%3}, [%4];" \
                 : "=r"(r0), "=r"(r1), "=r"(r2), "=r"(r3) : "r"(addr))
#define LDSM4T(r0, r1, r2, r3, addr) \
    asm volatile("ldmatrix.sync.aligned.m8n8.x4.trans.shared.b16 {%0,%1,%2,%3}, [%4];" \
                 : "=r"(r0), "=r"(r1), "=r"(r2), "=r"(r3) : "r"(addr))
#define MMA168(c0, c1, c2, c3, a0, a1, a2, a3, b0, b1) \
    asm volatile("mma.sync.aligned.m16n8k16.row.col.f32.f16.f16.f32 " \
                 "{%0,%1,%2,%3},{%4,%5,%6,%7},{%8,%9},{%0,%1,%2,%3};" \
                 : "+f"(c0), "+f"(c1), "+f"(c2), "+f"(c3) \
                 : "r"(a0), "r"(a1), "r"(a2), "r"(a3), "r"(b0), "r"(b1))

__device__ __forceinline__ unsigned smem_u32(const void* p)
{
    return (unsigned)__cvta_generic_to_shared(p);
}
__device__ __forceinline__ unsigned pack_h2(float a, float b)
{
    __half2 h = __floats2half2_rn(a, b);
    return *reinterpret_cast<unsigned*>(&h);
}

// fused fp32 -> fp16 for all four weight tensors
#define N4_QKV (3*D_MODEL*D_MODEL/4)
#define N4_OUT (D_MODEL*D_MODEL/4)
#define N4_FF1 (D_FF*D_MODEL/4)
#define N4_FF2 (D_MODEL*D_FF/4)
__global__ void __launch_bounds__(256) f2h_all(const float* __restrict__ w0,
                                               const float* __restrict__ w1,
                                               const float* __restrict__ w2,
                                               const float* __restrict__ w3,
                                               __half* __restrict__ o0,
                                               __half* __restrict__ o1,
                                               __half* __restrict__ o2,
                                               __half* __restrict__ o3)
{
    int i = blockIdx.x * 256 + threadIdx.x;
    const float* in;
    __half* out;
    int k;
    if (i < N4_QKV) {
        in = w0; out = o0; k = i;
    } else if (i < N4_QKV + N4_OUT) {
        in = w1; out = o1; k = i - N4_QKV;
    } else if (i < N4_QKV + N4_OUT + N4_FF1) {
        in = w2; out = o2; k = i - N4_QKV - N4_OUT;
    } else if (i < N4_QKV + N4_OUT + N4_FF1 + N4_FF2) {
        in = w3; out = o3; k = i - N4_QKV - N4_OUT - N4_FF1;
    } else {
        return;
    }
    float4 v = reinterpret_cast<const float4*>(in)[k];
    reinterpret_cast<__half2*>(out)[k * 2 + 0] = __floats2half2_rn(v.x, v.y);
    reinterpret_cast<__half2*>(out)[k * 2 + 1] = __floats2half2_rn(v.z, v.w);
}

// LayerNorm, one block per row of 512, half output
__global__ void __launch_bounds__(128) ln_kernel(const float* __restrict__ x,
                                                 const float* __restrict__ w,
                                                 const float* __restrict__ b,
                                                 __half* __restrict__ y)
{
    int row = blockIdx.x;
    int t = threadIdx.x;
    const float4* xr = reinterpret_cast<const float4*>(x) + (size_t)row * 128;
    float4 v = xr[t];
    float s  = v.x + v.y + v.z + v.w;
    float ss = v.x*v.x + v.y*v.y + v.z*v.z + v.w*v.w;
    #pragma unroll
    for (int off = 16; off >= 1; off >>= 1) {
        s  += __shfl_xor_sync(0xffffffffu, s,  off);
        ss += __shfl_xor_sync(0xffffffffu, ss, off);
    }
    __shared__ float rs[4], rss[4];
    int wid = t >> 5;
    if ((t & 31) == 0) { rs[wid] = s; rss[wid] = ss; }
    __syncthreads();
    s  = rs[0] + rs[1] + rs[2] + rs[3];
    ss = rss[0] + rss[1] + rss[2] + rss[3];
    float mu  = s * (1.0f / 512.0f);
    float var = ss * (1.0f / 512.0f) - mu * mu;
    float r   = rsqrtf(var + 1e-5f);
    float4 w4 = reinterpret_cast<const float4*>(w)[t];
    float4 b4 = reinterpret_cast<const float4*>(b)[t];
    __half2* yr = reinterpret_cast<__half2*>(y) + (size_t)row * 256;
    yr[t * 2 + 0] = __floats2half2_rn((v.x - mu) * r * w4.x + b4.x,
                                      (v.y - mu) * r * w4.y + b4.y);
    yr[t * 2 + 1] = __floats2half2_rn((v.z - mu) * r * w4.z + b4.z,
                                      (v.w - mu) * r * w4.w + b4.w);
}

// RoPE table
__global__ void __launch_bounds__(256) rope_tab_kernel(float2* __restrict__ tab)
{
    int idx = blockIdx.x * 256 + threadIdx.x;
    int s = idx >> 5;
    int i = idx & 31;
    double freq = 1.0 / pow(10000.0, (double)i / 32.0);
    float ang = (float)((double)s * freq);
    tab[idx] = make_float2(cosf(ang), sinf(ang));
}

// raw mma NT GEMM (round-10 passing config): 128x128 tile, BK=64, 3-stage ring,
// 8 warps in 4x2, warp tile 32x64.
// OUTM: 0 = fp32 C (+resid), 1 = half Ch, 2 = fused rope split to Q/K/V
#define GSTAGE 16384u
#define GEMM_SMEM (6 * 16384)

template<bool RELU, bool RESID, int OUTM>
__global__ void __launch_bounds__(256) gemm_mma(const __half* __restrict__ A,
                                                const __half* __restrict__ W,
                                                const float* __restrict__ bias,
                                                const float* __restrict__ resid,
                                                float* __restrict__ C,
                                                __half* __restrict__ Ch,
                                                __half* __restrict__ Qp,
                                                __half* __restrict__ Kp,
                                                __half* __restrict__ Vp,
                                                const float2* __restrict__ tab,
                                                int M, int N, int K)
{
    extern __shared__ __half smg[];
    unsigned aA = smem_u32(smg);
    unsigned aB = aA + 3 * GSTAGE;
    int tid = threadIdx.x;
    int lane = tid & 31;
    int wid = tid >> 5;
    int wr = wid >> 1;
    int wc = wid & 1;
    int lr = lane & 7;
    int lg = lane >> 3;
    int bm = blockIdx.y * 128;
    int bn = blockIdx.x * 128;
    int nK = K >> 6;

    const __half* Ag = A + (size_t)bm * K;
    const __half* Wg = W + (size_t)bn * K;

    float acc[2][8][4];
    #pragma unroll
    for (int i = 0; i < 2; i++) {
        #pragma unroll
        for (int j = 0; j < 8; j++) {
            acc[i][j][0] = 0.0f; acc[i][j][1] = 0.0f;
            acc[i][j][2] = 0.0f; acc[i][j][3] = 0.0f;
        }
    }

    // prologue: stages 0 and 1
    for (int st = 0; st < 2; st++) {
        unsigned dA = aA + (unsigned)st * GSTAGE;
        unsigned dB = aB + (unsigned)st * GSTAGE;
        int k0 = st * 64;
        #pragma unroll
        for (int i2 = 0; i2 < 4; i2++) {
            int idx = tid + i2 * 256;
            int rr = idx >> 3;
            int cc = idx & 7;
            CP16(dA + rr * 128 + ((cc ^ (rr & 7)) << 4), Ag + (size_t)rr * K + k0 + cc * 8);
            CP16(dB + rr * 128 + ((cc ^ (rr & 7)) << 4), Wg + (size_t)rr * K + k0 + cc * 8);
        }
        CPCOMMIT();
    }

    for (int kt = 0; kt < nK; kt++) {
        if (kt < nK - 1) {
            CPWAIT1();
        } else {
            CPWAIT0();
        }
        __syncthreads();
        if (kt + 2 < nK) {
            int st = (kt + 2) % 3;
            unsigned dA = aA + (unsigned)st * GSTAGE;
            unsigned dB = aB + (unsigned)st * GSTAGE;
            int k0 = (kt + 2) * 64;
            #pragma unroll
            for (int i2 = 0; i2 < 4; i2++) {
                int idx = tid + i2 * 256;
                int rr = idx >> 3;
                int cc = idx & 7;
                CP16(dA + rr * 128 + ((cc ^ (rr & 7)) << 4), Ag + (size_t)rr * K + k0 + cc * 8);
                CP16(dB + rr * 128 + ((cc ^ (rr & 7)) << 4), Wg + (size_t)rr * K + k0 + cc * 8);
            }
            CPCOMMIT();
        }
        unsigned cA = aA + (unsigned)(kt % 3) * GSTAGE;
        unsigned cB = aB + (unsigned)(kt % 3) * GSTAGE;
        #pragma unroll
        for (int kc = 0; kc < 4; kc++) {
            unsigned af0[4], af1[4];
            int arow = wr * 32 + ((lg & 1) << 3) + lr;
            int ach = kc * 2 + (lg >> 1);
            LDSM4(af0[0], af0[1], af0[2], af0[3],
                  cA + arow * 128 + ((ach ^ (arow & 7)) << 4));
            int arow2 = arow + 16;
            LDSM4(af1[0], af1[1], af1[2], af1[3],
                  cA + arow2 * 128 + ((ach ^ (arow2 & 7)) << 4));
            #pragma unroll
            for (int jj = 0; jj < 4; jj++) {
                int brow = wc * 64 + jj * 16 + ((lg >> 1) << 3) + lr;
                int bch = kc * 2 + (lg & 1);
                unsigned b0, b1, b2, b3;
                LDSM4(b0, b1, b2, b3, cB + brow * 128 + ((bch ^ (brow & 7)) << 4));
                MMA168(acc[0][2*jj][0], acc[0][2*jj][1], acc[0][2*jj][2], acc[0][2*jj][3],
                       af0[0], af0[1], af0[2], af0[3], b0, b1);
                MMA168(acc[0][2*jj+1][0], acc[0][2*jj+1][1], acc[0][2*jj+1][2], acc[0][2*jj+1][3],
                       af0[0], af0[1], af0[2], af0[3], b2, b3);
                MMA168(acc[1][2*jj][0], acc[1][2*jj][1], acc[1][2*jj][2], acc[1][2*jj][3],
                       af1[0], af1[1], af1[2], af1[3], b0, b1);
                MMA168(acc[1][2*jj+1][0], acc[1][2*jj+1][1], acc[1][2*jj+1][2], acc[1][2*jj+1][3],
                       af1[0], af1[1], af1[2], af1[3], b2, b3);
            }
        }
    }

    // epilogue straight from registers
    #pragma unroll
    for (int i = 0; i < 2; i++) {
        int r1 = bm + wr * 32 + i * 16 + (lane >> 2);
        int r2 = r1 + 8;
        #pragma unroll
        for (int j = 0; j < 8; j++) {
            int gc = bn + wc * 64 + j * 8 + (lane & 3) * 2;
            float2 bb = *reinterpret_cast<const float2*>(&bias[gc]);
            float c0 = acc[i][j][0] + bb.x;
            float c1 = acc[i][j][1] + bb.y;
            float c2 = acc[i][j][2] + bb.x;
            float c3 = acc[i][j][3] + bb.y;
            if (RELU) {
                c0 = fmaxf(c0, 0.0f); c1 = fmaxf(c1, 0.0f);
                c2 = fmaxf(c2, 0.0f); c3 = fmaxf(c3, 0.0f);
            }
            if (OUTM == 0) {
                if (RESID) {
                    float2 rv1 = *reinterpret_cast<const float2*>(&resid[(size_t)r1 * N + gc]);
                    float2 rv2 = *reinterpret_cast<const float2*>(&resid[(size_t)r2 * N + gc]);
                    c0 += rv1.x; c1 += rv1.y;
                    c2 += rv2.x; c3 += rv2.y;
                }
                *reinterpret_cast<float2*>(&C[(size_t)r1 * N + gc]) = make_float2(c0, c1);
                *reinterpret_cast<float2*>(&C[(size_t)r2 * N + gc]) = make_float2(c2, c3);
            } else if (OUTM == 1) {
                *reinterpret_cast<__half2*>(&Ch[(size_t)r1 * N + gc]) = __floats2half2_rn(c0, c1);
                *reinterpret_cast<__half2*>(&Ch[(size_t)r2 * N + gc]) = __floats2half2_rn(c2, c3);
            } else {
                int type = gc >> 9;
                int head = (gc >> 6) & 7;
                int d    = gc & 63;
                int s1 = r1 & (SEQ - 1);
                int s2 = r2 & (SEQ - 1);
                int bi1 = r1 >> 12;
                int bi2 = r2 >> 12;
                size_t oo1 = ((((size_t)bi1 * 8 + head) * SEQ) + s1) * 64 + d;
                size_t oo2 = ((((size_t)bi2 * 8 + head) * SEQ) + s2) * 64 + d;
                if (type == 2) {
                    *reinterpret_cast<__half2*>(&Vp[oo1]) = __floats2half2_rn(c0, c1);
                    *reinterpret_cast<__half2*>(&Vp[oo2]) = __floats2half2_rn(c2, c3);
                } else {
                    float2 cs1 = tab[s1 * 32 + (d >> 1)];
                    float2 cs2 = tab[s2 * 32 + (d >> 1)];
                    float x1 = c0 * cs1.x - c1 * cs1.y;
                    float y1 = c0 * cs1.y + c1 * cs1.x;
                    float x2 = c2 * cs2.x - c3 * cs2.y;
                    float y2 = c2 * cs2.y + c3 * cs2.x;
                    if (type == 0) {
                        *reinterpret_cast<__half2*>(&Qp[oo1]) =
                            __floats2half2_rn(x1 * 0.125f, y1 * 0.125f);
                        *reinterpret_cast<__half2*>(&Qp[oo2]) =
                            __floats2half2_rn(x2 * 0.125f, y2 * 0.125f);
                    } else {
                        *reinterpret_cast<__half2*>(&Kp[oo1]) = __floats2half2_rn(x1, y1);
                        *reinterpret_cast<__half2*>(&Kp[oo2]) = __floats2half2_rn(x2, y2);
                    }
                }
            }
        }
    }
}

// register-resident causal flash attention, Q tile 128 rows, 256 threads (8 warps),
// KV tile 64, per-warp logic identical to round-10 version.
// dynamic smem layout (bytes): Q 0..16384, K0 16384, K1 24576, V0 32768, V1 40960
#define FL_SMEM 49152

__global__ void __launch_bounds__(256) flash_mma(const __half* __restrict__ Qg,
                                                 const __half* __restrict__ Kg,
                                                 const __half* __restrict__ Vg,
                                                 __half* __restrict__ ctx)
{
    extern __shared__ char fsm[];
    unsigned aQ  = smem_u32(fsm);
    unsigned aK0 = aQ + 16384;
    unsigned aK1 = aQ + 24576;
    unsigned aV0 = aQ + 32768;
    unsigned aV1 = aQ + 40960;

    int qt = (int)gridDim.x - 1 - blockIdx.x;   // 128-row q tile, long blocks first
    int bh = blockIdx.y;
    int bb = bh >> 3;
    int hh = bh & 7;
    const __half* Qb = Qg + ((size_t)bh * SEQ + qt * 128) * 64;
    const __half* Kb = Kg + (size_t)bh * SEQ * 64;
    const __half* Vb = Vg + (size_t)bh * SEQ * 64;

    int tid = threadIdx.x;
    int lane = tid & 31;
    int wq = tid >> 5;          // 0..7, warp owns q rows wq*16..wq*16+15
    int lr = lane & 7;
    int lg = lane >> 3;

    // load Q tile (128 rows) + first K/V tile (64 rows)
    {
        #pragma unroll
        for (int i = 0; i < 4; i++) {
            int idx = tid + i * 256;          // 1024 chunks of Q
            int r = idx >> 3;
            int c = idx & 7;
            CP16(aQ + r * 128 + ((c ^ (r & 7)) << 4), Qb + (size_t)r * 64 + c * 8);
        }
        #pragma unroll
        for (int i = 0; i < 2; i++) {
            int idx = tid + i * 256;          // 512 chunks of K/V
            int r = idx >> 3;
            int c = idx & 7;
            CP16(aK0 + r * 128 + ((c ^ (r & 7)) << 4), Kb + (size_t)r * 64 + c * 8);
            CP16(aV0 + r * 128 + ((c ^ (r & 7)) << 4), Vb + (size_t)r * 64 + c * 8);
        }
    }
    CPCOMMIT();
    CPWAIT0();
    __syncthreads();

    unsigned qa[4][4];
    #pragma unroll
    for (int kc = 0; kc < 4; kc++) {
        int qrow = wq * 16 + ((lg & 1) << 3) + lr;
        int qch  = kc * 2 + (lg >> 1);
        LDSM4(qa[kc][0], qa[kc][1], qa[kc][2], qa[kc][3],
              aQ + qrow * 128 + ((qch ^ (qrow & 7)) << 4));
    }

    float O[8][4];
    #pragma unroll
    for (int j = 0; j < 8; j++) {
        O[j][0] = 0.0f; O[j][1] = 0.0f; O[j][2] = 0.0f; O[j][3] = 0.0f;
    }
    float m1 = -1e30f;
    float m2 = -1e30f;
    float l1 = 0.0f;
    float l2 = 0.0f;

    int grow1 = qt * 128 + wq * 16 + (lane >> 2);
    int grow2 = grow1 + 8;
    int nkv = 2 * qt + 2;

    for (int kt = 0; kt < nkv; ++kt) {
        unsigned curK = (kt & 1) ? aK1 : aK0;
        unsigned curV = (kt & 1) ? aV1 : aV0;
        unsigned nxtK = (kt & 1) ? aK0 : aK1;
        unsigned nxtV = (kt & 1) ? aV0 : aV1;
        if (kt + 1 < nkv) {
            const __half* Kn = Kb + (size_t)(kt + 1) * 4096;
            const __half* Vn = Vb + (size_t)(kt + 1) * 4096;
            #pragma unroll
            for (int i = 0; i < 2; i++) {
                int idx = tid + i * 256;
                int r = idx >> 3;
                int c = idx & 7;
                CP16(nxtK + r * 128 + ((c ^ (r & 7)) << 4), Kn + (size_t)r * 64 + c * 8);
                CP16(nxtV + r * 128 + ((c ^ (r & 7)) << 4), Vn + (size_t)r * 64 + c * 8);
            }
            CPCOMMIT();
        }

        float S[8][4];
        #pragma unroll
        for (int j = 0; j < 8; j++) {
            S[j][0] = 0.0f; S[j][1] = 0.0f; S[j][2] = 0.0f; S[j][3] = 0.0f;
        }
        #pragma unroll
        for (int ng = 0; ng < 4; ng++) {
            #pragma unroll
            for (int kc = 0; kc < 4; kc++) {
                int krow = ng * 16 + ((lg >> 1) << 3) + lr;
                int kch  = kc * 2 + (lg & 1);
                unsigned b0, b1, b2, b3;
                LDSM4(b0, b1, b2, b3, curK + krow * 128 + ((kch ^ (krow & 7)) << 4));
                MMA168(S[ng * 2][0], S[ng * 2][1], S[ng * 2][2], S[ng * 2][3],
                       qa[kc][0], qa[kc][1], qa[kc][2], qa[kc][3], b0, b1);
                MMA168(S[ng * 2 + 1][0], S[ng * 2 + 1][1], S[ng * 2 + 1][2], S[ng * 2 + 1][3],
                       qa[kc][0], qa[kc][1], qa[kc][2], qa[kc][3], b2, b3);
            }
        }

        // causal mask on the last two (boundary) KV tiles; elementwise test
        // self-disables for warps whose rows are fully visible
        if (kt >= 2 * qt) {
            #pragma unroll
            for (int j = 0; j < 8; j++) {
                int col = kt * 64 + j * 8 + (lane & 3) * 2;
                if (col     > grow1) S[j][0] = -1e30f;
                if (col + 1 > grow1) S[j][1] = -1e30f;
                if (col     > grow2) S[j][2] = -1e30f;
                if (col + 1 > grow2) S[j][3] = -1e30f;
            }
        }

        float mx1 = -1e30f;
        float mx2 = -1e30f;
        #pragma unroll
        for (int j = 0; j < 8; j++) {
            mx1 = fmaxf(mx1, fmaxf(S[j][0], S[j][1]));
            mx2 = fmaxf(mx2, fmaxf(S[j][2], S[j][3]));
        }
        mx1 = fmaxf(mx1, __shfl_xor_sync(0xffffffffu, mx1, 1));
        mx1 = fmaxf(mx1, __shfl_xor_sync(0xffffffffu, mx1, 2));
        mx2 = fmaxf(mx2, __shfl_xor_sync(0xffffffffu, mx2, 1));
        mx2 = fmaxf(mx2, __shfl_xor_sync(0xffffffffu, mx2, 2));
        float mn1 = fmaxf(m1, mx1);
        float mn2 = fmaxf(m2, mx2);
        float al1 = __expf(m1 - mn1);
        float al2 = __expf(m2 - mn2);
        float sm1 = 0.0f;
        float sm2 = 0.0f;
        #pragma unroll
        for (int j = 0; j < 8; j++) {
            S[j][0] = __expf(S[j][0] - mn1);
            S[j][1] = __expf(S[j][1] - mn1);
            S[j][2] = __expf(S[j][2] - mn2);
            S[j][3] = __expf(S[j][3] - mn2);
            sm1 += S[j][0] + S[j][1];
            sm2 += S[j][2] + S[j][3];
        }
        sm1 += __shfl_xor_sync(0xffffffffu, sm1, 1);
        sm1 += __shfl_xor_sync(0xffffffffu, sm1, 2);
        sm2 += __shfl_xor_sync(0xffffffffu, sm2, 1);
        sm2 += __shfl_xor_sync(0xffffffffu, sm2, 2);
        l1 = l1 * al1 + sm1;
        l2 = l2 * al2 + sm2;
        m1 = mn1;
        m2 = mn2;
        #pragma unroll
        for (int j = 0; j < 8; j++) {
            O[j][0] *= al1; O[j][1] *= al1;
            O[j][2] *= al2; O[j][3] *= al2;
        }

        unsigned pa[4][4];
        #pragma unroll
        for (int kc = 0; kc < 4; kc++) {
            pa[kc][0] = pack_h2(S[2 * kc][0],     S[2 * kc][1]);
            pa[kc][1] = pack_h2(S[2 * kc][2],     S[2 * kc][3]);
            pa[kc][2] = pack_h2(S[2 * kc + 1][0], S[2 * kc + 1][1]);
            pa[kc][3] = pack_h2(S[2 * kc + 1][2], S[2 * kc + 1][3]);
        }

        #pragma unroll
        for (int dg = 0; dg < 4; dg++) {
            #pragma unroll
            for (int tc = 0; tc < 4; tc++) {
                int vrow = tc * 16 + ((lg & 1) << 3) + lr;
                int vch  = dg * 2 + (lg >> 1);
                unsigned v0, v1, v2, v3;
                LDSM4T(v0, v1, v2, v3, curV + vrow * 128 + ((vch ^ (vrow & 7)) << 4));
                MMA168(O[dg * 2][0], O[dg * 2][1], O[dg * 2][2], O[dg * 2][3],
                       pa[tc][0], pa[tc][1], pa[tc][2], pa[tc][3], v0, v1);
                MMA168(O[dg * 2 + 1][0], O[dg * 2 + 1][1], O[dg * 2 + 1][2], O[dg * 2 + 1][3],
                       pa[tc][0], pa[tc][1], pa[tc][2], pa[tc][3], v2, v3);
            }
        }

        if (kt + 1 < nkv) {
            CPWAIT0();
            __syncthreads();
        }
    }

    float inv1 = 1.0f / l1;
    float inv2 = 1.0f / l2;
    size_t base1 = ((size_t)bb * SEQ + grow1) * 512 + hh * 64;
    size_t base2 = ((size_t)bb * SEQ + grow2) * 512 + hh * 64;
    #pragma unroll
    for (int j = 0; j < 8; j++) {
        int col = j * 8 + (lane & 3) * 2;
        *reinterpret_cast<__half2*>(&ctx[base1 + col]) =
            __floats2half2_rn(O[j][0] * inv1, O[j][1] * inv1);
        *reinterpret_cast<__half2*>(&ctx[base2 + col]) =
            __floats2half2_rn(O[j][2] * inv2, O[j][3] * inv2);
    }
}

extern "C" void kernel_launch(void* const* d_in, const int* in_sizes, int n_in,
                              void* d_out, int out_size)
{
    const float* src      = (const float*)d_in[0];
    const float* ln_w     = (const float*)d_in[1];
    const float* ln_b     = (const float*)d_in[2];
    const float* wqkv_w   = (const float*)d_in[3];
    const float* wqkv_b   = (const float*)d_in[4];
    const float* out_w    = (const float*)d_in[5];
    const float* out_b    = (const float*)d_in[6];
    const float* ffn_ln_w = (const float*)d_in[7];
    const float* ffn_ln_b = (const float*)d_in[8];
    const float* ff1_w    = (const float*)d_in[9];
    const float* ff1_b    = (const float*)d_in[10];
    const float* ff2_w    = (const float*)d_in[11];
    const float* ff2_b    = (const float*)d_in[12];
    float* out = (float*)d_out;

    __half *xln, *Q, *K, *V, *ctx, *hid, *wqkvh, *outwh, *ff1h, *ff2h;
    float *src2;
    float2* tab;
    cudaGetSymbolAddress((void**)&xln,   g_xln_h);
    cudaGetSymbolAddress((void**)&Q,     g_Qh);
    cudaGetSymbolAddress((void**)&K,     g_Kh);
    cudaGetSymbolAddress((void**)&V,     g_Vh);
    cudaGetSymbolAddress((void**)&ctx,   g_ctx_h);
    cudaGetSymbolAddress((void**)&src2,  g_src2);
    cudaGetSymbolAddress((void**)&hid,   g_hid_h);
    cudaGetSymbolAddress((void**)&tab,   g_rope);
    cudaGetSymbolAddress((void**)&wqkvh, g_wqkv_h);
    cudaGetSymbolAddress((void**)&outwh, g_outw_h);
    cudaGetSymbolAddress((void**)&ff1h,  g_ff1_h);
    cudaGetSymbolAddress((void**)&ff2h,  g_ff2_h);

    cudaFuncSetAttribute(gemm_mma<false, false, 2>,
                         cudaFuncAttributeMaxDynamicSharedMemorySize, GEMM_SMEM);
    cudaFuncSetAttribute(gemm_mma<false, true, 0>,
                         cudaFuncAttributeMaxDynamicSharedMemorySize, GEMM_SMEM);
    cudaFuncSetAttribute(gemm_mma<true, false, 1>,
                         cudaFuncAttributeMaxDynamicSharedMemorySize, GEMM_SMEM);
    cudaFuncSetAttribute(flash_mma,
                         cudaFuncAttributeMaxDynamicSharedMemorySize, FL_SMEM);

    int n4_total = N4_QKV + N4_OUT + N4_FF1 + N4_FF2;
    f2h_all<<<(n4_total + 255) / 256, 256>>>(wqkv_w, out_w, ff1_w, ff2_w,
                                             wqkvh, outwh, ff1h, ff2h);
    rope_tab_kernel<<<(SEQ * 32) / 256, 256>>>(tab);
    ln_kernel<<<ROWS, 128>>>(src, ln_w, ln_b, xln);

    // QKV projection with fused rope + split
    gemm_mma<false, false, 2><<<dim3(12, 64), 256, GEMM_SMEM>>>(
        xln, wqkvh, wqkv_b, nullptr, nullptr, nullptr, Q, K, V, tab,
        ROWS, 3 * D_MODEL, D_MODEL);

    flash_mma<<<dim3(SEQ / 128, BH), 256, FL_SMEM>>>(Q, K, V, ctx);

    gemm_mma<false, true, 0><<<dim3(4, 64), 256, GEMM_SMEM>>>(
        ctx, outwh, out_b, src, src2, nullptr, nullptr, nullptr, nullptr, nullptr,
        ROWS, D_MODEL, D_MODEL);

    ln_kernel<<<ROWS, 128>>>(src2, ffn_ln_w, ffn_ln_b, xln);

    gemm_mma<true, false, 1><<<dim3(16, 64), 256, GEMM_SMEM>>>(
        xln, ff1h, ff1_b, nullptr, nullptr, hid, nullptr, nullptr, nullptr, nullptr,
        ROWS, D_FF, D_MODEL);

    gemm_mma<false, true, 0><<<dim3(4, 64), 256, GEMM_SMEM>>>(
        hid, ff2h, ff2_b, src2, out, nullptr, nullptr, nullptr, nullptr, nullptr,
        ROWS, D_MODEL, D_FF);
}

// round 14
// speedup vs baseline: 1.1140x; 1.0311x over previous
#include <cuda_runtime.h>
#include <cuda_fp16.h>
#include <math.h>

#define D_MODEL 512
#define N_HEADS 8
#define HEAD_DIM 64
#define D_FF 2048
#define SEQ 4096
#define BATCH 2
#define ROWS (BATCH*SEQ)
#define BH (BATCH*N_HEADS)

// scratch buffers (no allocation allowed)
__device__ __half  g_xln_h [ROWS*D_MODEL];
__device__ __half  g_Qh    [BH*SEQ*HEAD_DIM];
__device__ __half  g_Kh    [BH*SEQ*HEAD_DIM];
__device__ __half  g_Vh    [BH*SEQ*HEAD_DIM];
__device__ __half  g_ctx_h [ROWS*D_MODEL];
__device__ float   g_src2  [ROWS*D_MODEL];
__device__ __half  g_hid_h [ROWS*D_FF];
__device__ float2  g_rope  [SEQ*32];
__device__ __half  g_wqkv_h[3*D_MODEL*D_MODEL];
__device__ __half  g_outw_h[D_MODEL*D_MODEL];
__device__ __half  g_ff1_h [D_FF*D_MODEL];
__device__ __half  g_ff2_h [D_MODEL*D_FF];

// asm macros
#define CP16(dst, src) \
    asm volatile("cp.async.cg.shared.global [%0], [%1], 16;" :: "r"(dst), "l"(src))
#define CPCOMMIT() asm volatile("cp.async.commit_group;")
#define CPWAIT0()  asm volatile("cp.async.wait_group 0;")
#define CPWAIT1()  asm volatile("cp.async.wait_group 1;")
#define LDSM4(r0, r1, r2, r3, addr) \
    asm volatile("ldmatrix.sync.aligned.m8n8.x4.shared.b16 {%0,%1,%2,%3}, [%4];" \
                 : "=r"(r0), "=r"(r1), "=r"(r2), "=r"(r3) : "r"(addr))
#define LDSM4T(r0, r1, r2, r3, addr) \
    asm volatile("ldmatrix.sync.aligned.m8n8.x4.trans.shared.b16 {%0,%1,%2,%3}, [%4];" \
                 : "=r"(r0), "=r"(r1), "=r"(r2), "=r"(r3) : "r"(addr))
#define MMA168(c0, c1, c2, c3, a0, a1, a2, a3, b0, b1) \
    asm volatile("mma.sync.aligned.m16n8k16.row.col.f32.f16.f16.f32 " \
                 "{%0,%1,%2,%3},{%4,%5,%6,%7},{%8,%9},{%0,%1,%2,%3};" \
                 : "+f"(c0), "+f"(c1), "+f"(c2), "+f"(c3) \
                 : "r"(a0), "r"(a1), "r"(a2), "r"(a3), "r"(b0), "r"(b1))

__device__ __forceinline__ unsigned smem_u32(const void* p)
{
    return (unsigned)__cvta_generic_to_shared(p);
}
__device__ __forceinline__ unsigned pack_h2(float a, float b)
{
    __half2 h = __floats2half2_rn(a, b);
    return *reinterpret_cast<unsigned*>(&h);
}

// fused fp32 -> fp16 for all four weight tensors
#define N4_QKV (3*D_MODEL*D_MODEL/4)
#define N4_OUT (D_MODEL*D_MODEL/4)
#define N4_FF1 (D_FF*D_MODEL/4)
#define N4_FF2 (D_MODEL*D_FF/4)
__global__ void __launch_bounds__(256) f2h_all(const float* __restrict__ w0,
                                               const float* __restrict__ w1,
                                               const float* __restrict__ w2,
                                               const float* __restrict__ w3,
                                               __half* __restrict__ o0,
                                               __half* __restrict__ o1,
                                               __half* __restrict__ o2,
                                               __half* __restrict__ o3)
{
    int i = blockIdx.x * 256 + threadIdx.x;
    const float* in;
    __half* out;
    int k;
    if (i < N4_QKV) {
        in = w0; out = o0; k = i;
    } else if (i < N4_QKV + N4_OUT) {
        in = w1; out = o1; k = i - N4_QKV;
    } else if (i < N4_QKV + N4_OUT + N4_FF1) {
        in = w2; out = o2; k = i - N4_QKV - N4_OUT;
    } else if (i < N4_QKV + N4_OUT + N4_FF1 + N4_FF2) {
        in = w3; out = o3; k = i - N4_QKV - N4_OUT - N4_FF1;
    } else {
        return;
    }
    float4 v = reinterpret_cast<const float4*>(in)[k];
    reinterpret_cast<__half2*>(out)[k * 2 + 0] = __floats2half2_rn(v.x, v.y);
    reinterpret_cast<__half2*>(out)[k * 2 + 1] = __floats2half2_rn(v.z, v.w);
}

// LayerNorm, one block per row of 512, half output
__global__ void __launch_bounds__(128) ln_kernel(const float* __restrict__ x,
                                                 const float* __restrict__ w,
                                                 const float* __restrict__ b,
                                                 __half* __restrict__ y)
{
    int row = blockIdx.x;
    int t = threadIdx.x;
    const float4* xr = reinterpret_cast<const float4*>(x) + (size_t)row * 128;
    float4 v = xr[t];
    float s  = v.x + v.y + v.z + v.w;
    float ss = v.x*v.x + v.y*v.y + v.z*v.z + v.w*v.w;
    #pragma unroll
    for (int off = 16; off >= 1; off >>= 1) {
        s  += __shfl_xor_sync(0xffffffffu, s,  off);
        ss += __shfl_xor_sync(0xffffffffu, ss, off);
    }
    __shared__ float rs[4], rss[4];
    int wid = t >> 5;
    if ((t & 31) == 0) { rs[wid] = s; rss[wid] = ss; }
    __syncthreads();
    s  = rs[0] + rs[1] + rs[2] + rs[3];
    ss = rss[0] + rss[1] + rss[2] + rss[3];
    float mu  = s * (1.0f / 512.0f);
    float var = ss * (1.0f / 512.0f) - mu * mu;
    float r   = rsqrtf(var + 1e-5f);
    float4 w4 = reinterpret_cast<const float4*>(w)[t];
    float4 b4 = reinterpret_cast<const float4*>(b)[t];
    __half2* yr = reinterpret_cast<__half2*>(y) + (size_t)row * 256;
    yr[t * 2 + 0] = __floats2half2_rn((v.x - mu) * r * w4.x + b4.x,
                                      (v.y - mu) * r * w4.y + b4.y);
    yr[t * 2 + 1] = __floats2half2_rn((v.z - mu) * r * w4.z + b4.z,
                                      (v.w - mu) * r * w4.w + b4.w);
}

// RoPE table
__global__ void __launch_bounds__(256) rope_tab_kernel(float2* __restrict__ tab)
{
    int idx = blockIdx.x * 256 + threadIdx.x;
    int s = idx >> 5;
    int i = idx & 31;
    double freq = 1.0 / pow(10000.0, (double)i / 32.0);
    float ang = (float)((double)s * freq);
    tab[idx] = make_float2(cosf(ang), sinf(ang));
}

// raw mma NT GEMM: 128x128 tile, BK=64, 3-stage ring, 8 warps in 4x2,
// warp tile 32x64, B-fragment double-buffer software pipeline.
// OUTM: 0 = fp32 C (+resid), 1 = half Ch, 2 = fused rope split to Q/K/V
// (Q pre-scaled by 0.125*log2(e) for exp2-domain softmax in flash)
#define GSTAGE 16384u
#define GEMM_SMEM (6 * 16384)
#define QSCALE 0.18033688f

template<bool RELU, bool RESID, int OUTM>
__global__ void __launch_bounds__(256, 2) gemm_mma(const __half* __restrict__ A,
                                                   const __half* __restrict__ W,
                                                   const float* __restrict__ bias,
                                                   const float* __restrict__ resid,
                                                   float* __restrict__ C,
                                                   __half* __restrict__ Ch,
                                                   __half* __restrict__ Qp,
                                                   __half* __restrict__ Kp,
                                                   __half* __restrict__ Vp,
                                                   const float2* __restrict__ tab,
                                                   int M, int N, int K)
{
    extern __shared__ __half smg[];
    unsigned aA = smem_u32(smg);
    unsigned aB = aA + 3 * GSTAGE;
    int tid = threadIdx.x;
    int lane = tid & 31;
    int wid = tid >> 5;
    int wr = wid >> 1;
    int wc = wid & 1;
    int lr = lane & 7;
    int lg = lane >> 3;
    int bm = blockIdx.y * 128;
    int bn = blockIdx.x * 128;
    int nK = K >> 6;

    const __half* Ag = A + (size_t)bm * K;
    const __half* Wg = W + (size_t)bn * K;

    float acc[2][8][4];
    #pragma unroll
    for (int i = 0; i < 2; i++) {
        #pragma unroll
        for (int j = 0; j < 8; j++) {
            acc[i][j][0] = 0.0f; acc[i][j][1] = 0.0f;
            acc[i][j][2] = 0.0f; acc[i][j][3] = 0.0f;
        }
    }

    // prologue: stages 0 and 1
    for (int st = 0; st < 2; st++) {
        unsigned dA = aA + (unsigned)st * GSTAGE;
        unsigned dB = aB + (unsigned)st * GSTAGE;
        int k0 = st * 64;
        #pragma unroll
        for (int i2 = 0; i2 < 4; i2++) {
            int idx = tid + i2 * 256;
            int rr = idx >> 3;
            int cc = idx & 7;
            CP16(dA + rr * 128 + ((cc ^ (rr & 7)) << 4), Ag + (size_t)rr * K + k0 + cc * 8);
            CP16(dB + rr * 128 + ((cc ^ (rr & 7)) << 4), Wg + (size_t)rr * K + k0 + cc * 8);
        }
        CPCOMMIT();
    }

    for (int kt = 0; kt < nK; kt++) {
        if (kt < nK - 1) {
            CPWAIT1();
        } else {
            CPWAIT0();
        }
        __syncthreads();
        if (kt + 2 < nK) {
            int st = (kt + 2) % 3;
            unsigned dA = aA + (unsigned)st * GSTAGE;
            unsigned dB = aB + (unsigned)st * GSTAGE;
            int k0 = (kt + 2) * 64;
            #pragma unroll
            for (int i2 = 0; i2 < 4; i2++) {
                int idx = tid + i2 * 256;
                int rr = idx >> 3;
                int cc = idx & 7;
                CP16(dA + rr * 128 + ((cc ^ (rr & 7)) << 4), Ag + (size_t)rr * K + k0 + cc * 8);
                CP16(dB + rr * 128 + ((cc ^ (rr & 7)) << 4), Wg + (size_t)rr * K + k0 + cc * 8);
            }
            CPCOMMIT();
        }
        unsigned cA = aA + (unsigned)(kt % 3) * GSTAGE;
        unsigned cB = aB + (unsigned)(kt % 3) * GSTAGE;
        #pragma unroll
        for (int kc = 0; kc < 4; kc++) {
            unsigned af0[4], af1[4];
            int arow = wr * 32 + ((lg & 1) << 3) + lr;
            int ach = kc * 2 + (lg >> 1);
            LDSM4(af0[0], af0[1], af0[2], af0[3],
                  cA + arow * 128 + ((ach ^ (arow & 7)) << 4));
            int arow2 = arow + 16;
            LDSM4(af1[0], af1[1], af1[2], af1[3],
                  cA + arow2 * 128 + ((ach ^ (arow2 & 7)) << 4));
            int bch = kc * 2 + (lg & 1);
            // B fragment double buffer: prefetch jj+1 before MMAs on jj
            unsigned bfr[2][4];
            {
                int brow = wc * 64 + ((lg >> 1) << 3) + lr;
                LDSM4(bfr[0][0], bfr[0][1], bfr[0][2], bfr[0][3],
                      cB + brow * 128 + ((bch ^ (brow & 7)) << 4));
            }
            #pragma unroll
            for (int jj = 0; jj < 4; jj++) {
                int cur = jj & 1;
                if (jj < 3) {
                    int brow = wc * 64 + (jj + 1) * 16 + ((lg >> 1) << 3) + lr;
                    LDSM4(bfr[cur ^ 1][0], bfr[cur ^ 1][1], bfr[cur ^ 1][2], bfr[cur ^ 1][3],
                          cB + brow * 128 + ((bch ^ (brow & 7)) << 4));
                }
                MMA168(acc[0][2*jj][0], acc[0][2*jj][1], acc[0][2*jj][2], acc[0][2*jj][3],
                       af0[0], af0[1], af0[2], af0[3], bfr[cur][0], bfr[cur][1]);
                MMA168(acc[1][2*jj][0], acc[1][2*jj][1], acc[1][2*jj][2], acc[1][2*jj][3],
                       af1[0], af1[1], af1[2], af1[3], bfr[cur][0], bfr[cur][1]);
                MMA168(acc[0][2*jj+1][0], acc[0][2*jj+1][1], acc[0][2*jj+1][2], acc[0][2*jj+1][3],
                       af0[0], af0[1], af0[2], af0[3], bfr[cur][2], bfr[cur][3]);
                MMA168(acc[1][2*jj+1][0], acc[1][2*jj+1][1], acc[1][2*jj+1][2], acc[1][2*jj+1][3],
                       af1[0], af1[1], af1[2], af1[3], bfr[cur][2], bfr[cur][3]);
            }
        }
    }

    // epilogue straight from registers
    #pragma unroll
    for (int i = 0; i < 2; i++) {
        int r1 = bm + wr * 32 + i * 16 + (lane >> 2);
        int r2 = r1 + 8;
        #pragma unroll
        for (int j = 0; j < 8; j++) {
            int gc = bn + wc * 64 + j * 8 + (lane & 3) * 2;
            float2 bb = *reinterpret_cast<const float2*>(&bias[gc]);
            float c0 = acc[i][j][0] + bb.x;
            float c1 = acc[i][j][1] + bb.y;
            float c2 = acc[i][j][2] + bb.x;
            float c3 = acc[i][j][3] + bb.y;
            if (RELU) {
                c0 = fmaxf(c0, 0.0f); c1 = fmaxf(c1, 0.0f);
                c2 = fmaxf(c2, 0.0f); c3 = fmaxf(c3, 0.0f);
            }
            if (OUTM == 0) {
                if (RESID) {
                    float2 rv1 = *reinterpret_cast<const float2*>(&resid[(size_t)r1 * N + gc]);
                    float2 rv2 = *reinterpret_cast<const float2*>(&resid[(size_t)r2 * N + gc]);
                    c0 += rv1.x; c1 += rv1.y;
                    c2 += rv2.x; c3 += rv2.y;
                }
                *reinterpret_cast<float2*>(&C[(size_t)r1 * N + gc]) = make_float2(c0, c1);
                *reinterpret_cast<float2*>(&C[(size_t)r2 * N + gc]) = make_float2(c2, c3);
            } else if (OUTM == 1) {
                *reinterpret_cast<__half2*>(&Ch[(size_t)r1 * N + gc]) = __floats2half2_rn(c0, c1);
                *reinterpret_cast<__half2*>(&Ch[(size_t)r2 * N + gc]) = __floats2half2_rn(c2, c3);
            } else {
                int type = gc >> 9;
                int head = (gc >> 6) & 7;
                int d    = gc & 63;
                int s1 = r1 & (SEQ - 1);
                int s2 = r2 & (SEQ - 1);
                int bi1 = r1 >> 12;
                int bi2 = r2 >> 12;
                size_t oo1 = ((((size_t)bi1 * 8 + head) * SEQ) + s1) * 64 + d;
                size_t oo2 = ((((size_t)bi2 * 8 + head) * SEQ) + s2) * 64 + d;
                if (type == 2) {
                    *reinterpret_cast<__half2*>(&Vp[oo1]) = __floats2half2_rn(c0, c1);
                    *reinterpret_cast<__half2*>(&Vp[oo2]) = __floats2half2_rn(c2, c3);
                } else {
                    float2 cs1 = tab[s1 * 32 + (d >> 1)];
                    float2 cs2 = tab[s2 * 32 + (d >> 1)];
                    float x1 = c0 * cs1.x - c1 * cs1.y;
                    float y1 = c0 * cs1.y + c1 * cs1.x;
                    float x2 = c2 * cs2.x - c3 * cs2.y;
                    float y2 = c2 * cs2.y + c3 * cs2.x;
                    if (type == 0) {
                        *reinterpret_cast<__half2*>(&Qp[oo1]) =
                            __floats2half2_rn(x1 * QSCALE, y1 * QSCALE);
                        *reinterpret_cast<__half2*>(&Qp[oo2]) =
                            __floats2half2_rn(x2 * QSCALE, y2 * QSCALE);
                    } else {
                        *reinterpret_cast<__half2*>(&Kp[oo1]) = __floats2half2_rn(x1, y1);
                        *reinterpret_cast<__half2*>(&Kp[oo2]) = __floats2half2_rn(x2, y2);
                    }
                }
            }
        }
    }
}

// register-resident causal flash attention, Q tile 128 rows, 256 threads (8 warps),
// KV tile 64, exp2-domain softmax (Q pre-scaled by 0.125*log2e).
#define FL_SMEM 49152

__global__ void __launch_bounds__(256) flash_mma(const __half* __restrict__ Qg,
                                                 const __half* __restrict__ Kg,
                                                 const __half* __restrict__ Vg,
                                                 __half* __restrict__ ctx)
{
    extern __shared__ char fsm[];
    unsigned aQ  = smem_u32(fsm);
    unsigned aK0 = aQ + 16384;
    unsigned aK1 = aQ + 24576;
    unsigned aV0 = aQ + 32768;
    unsigned aV1 = aQ + 40960;

    int qt = (int)gridDim.x - 1 - blockIdx.x;
    int bh = blockIdx.y;
    int bb = bh >> 3;
    int hh = bh & 7;
    const __half* Qb = Qg + ((size_t)bh * SEQ + qt * 128) * 64;
    const __half* Kb = Kg + (size_t)bh * SEQ * 64;
    const __half* Vb = Vg + (size_t)bh * SEQ * 64;

    int tid = threadIdx.x;
    int lane = tid & 31;
    int wq = tid >> 5;
    int lr = lane & 7;
    int lg = lane >> 3;

    {
        #pragma unroll
        for (int i = 0; i < 4; i++) {
            int idx = tid + i * 256;
            int r = idx >> 3;
            int c = idx & 7;
            CP16(aQ + r * 128 + ((c ^ (r & 7)) << 4), Qb + (size_t)r * 64 + c * 8);
        }
        #pragma unroll
        for (int i = 0; i < 2; i++) {
            int idx = tid + i * 256;
            int r = idx >> 3;
            int c = idx & 7;
            CP16(aK0 + r * 128 + ((c ^ (r & 7)) << 4), Kb + (size_t)r * 64 + c * 8);
            CP16(aV0 + r * 128 + ((c ^ (r & 7)) << 4), Vb + (size_t)r * 64 + c * 8);
        }
    }
    CPCOMMIT();
    CPWAIT0();
    __syncthreads();

    unsigned qa[4][4];
    #pragma unroll
    for (int kc = 0; kc < 4; kc++) {
        int qrow = wq * 16 + ((lg & 1) << 3) + lr;
        int qch  = kc * 2 + (lg >> 1);
        LDSM4(qa[kc][0], qa[kc][1], qa[kc][2], qa[kc][3],
              aQ + qrow * 128 + ((qch ^ (qrow & 7)) << 4));
    }

    float O[8][4];
    #pragma unroll
    for (int j = 0; j < 8; j++) {
        O[j][0] = 0.0f; O[j][1] = 0.0f; O[j][2] = 0.0f; O[j][3] = 0.0f;
    }
    float m1 = -1e30f;
    float m2 = -1e30f;
    float l1 = 0.0f;
    float l2 = 0.0f;

    int grow1 = qt * 128 + wq * 16 + (lane >> 2);
    int grow2 = grow1 + 8;
    int nkv = 2 * qt + 2;

    for (int kt = 0; kt < nkv; ++kt) {
        unsigned curK = (kt & 1) ? aK1 : aK0;
        unsigned curV = (kt & 1) ? aV1 : aV0;
        unsigned nxtK = (kt & 1) ? aK0 : aK1;
        unsigned nxtV = (kt & 1) ? aV0 : aV1;
        if (kt + 1 < nkv) {
            const __half* Kn = Kb + (size_t)(kt + 1) * 4096;
            const __half* Vn = Vb + (size_t)(kt + 1) * 4096;
            #pragma unroll
            for (int i = 0; i < 2; i++) {
                int idx = tid + i * 256;
                int r = idx >> 3;
                int c = idx & 7;
                CP16(nxtK + r * 128 + ((c ^ (r & 7)) << 4), Kn + (size_t)r * 64 + c * 8);
                CP16(nxtV + r * 128 + ((c ^ (r & 7)) << 4), Vn + (size_t)r * 64 + c * 8);
            }
            CPCOMMIT();
        }

        float S[8][4];
        #pragma unroll
        for (int j = 0; j < 8; j++) {
            S[j][0] = 0.0f; S[j][1] = 0.0f; S[j][2] = 0.0f; S[j][3] = 0.0f;
        }
        #pragma unroll
        for (int ng = 0; ng < 4; ng++) {
            #pragma unroll
            for (int kc = 0; kc < 4; kc++) {
                int krow = ng * 16 + ((lg >> 1) << 3) + lr;
                int kch  = kc * 2 + (lg & 1);
                unsigned b0, b1, b2, b3;
                LDSM4(b0, b1, b2, b3, curK + krow * 128 + ((kch ^ (krow & 7)) << 4));
                MMA168(S[ng * 2][0], S[ng * 2][1], S[ng * 2][2], S[ng * 2][3],
                       qa[kc][0], qa[kc][1], qa[kc][2], qa[kc][3], b0, b1);
                MMA168(S[ng * 2 + 1][0], S[ng * 2 + 1][1], S[ng * 2 + 1][2], S[ng * 2 + 1][3],
                       qa[kc][0], qa[kc][1], qa[kc][2], qa[kc][3], b2, b3);
            }
        }

        if (kt >= 2 * qt) {
            #pragma unroll
            for (int j = 0; j < 8; j++) {
                int col = kt * 64 + j * 8 + (lane & 3) * 2;
                if (col     > grow1) S[j][0] = -1e30f;
                if (col + 1 > grow1) S[j][1] = -1e30f;
                if (col     > grow2) S[j][2] = -1e30f;
                if (col + 1 > grow2) S[j][3] = -1e30f;
            }
        }

        float mx1 = -1e30f;
        float mx2 = -1e30f;
        #pragma unroll
        for (int j = 0; j < 8; j++) {
            mx1 = fmaxf(mx1, fmaxf(S[j][0], S[j][1]));
            mx2 = fmaxf(mx2, fmaxf(S[j][2], S[j][3]));
        }
        mx1 = fmaxf(mx1, __shfl_xor_sync(0xffffffffu, mx1, 1));
        mx1 = fmaxf(mx1, __shfl_xor_sync(0xffffffffu, mx1, 2));
        mx2 = fmaxf(mx2, __shfl_xor_sync(0xffffffffu, mx2, 1));
        mx2 = fmaxf(mx2, __shfl_xor_sync(0xffffffffu, mx2, 2));
        float mn1 = fmaxf(m1, mx1);
        float mn2 = fmaxf(m2, mx2);
        float al1 = exp2f(m1 - mn1);
        float al2 = exp2f(m2 - mn2);
        float sm1 = 0.0f;
        float sm2 = 0.0f;
        #pragma unroll
        for (int j = 0; j < 8; j++) {
            S[j][0] = exp2f(S[j][0] - mn1);
            S[j][1] = exp2f(S[j][1] - mn1);
            S[j][2] = exp2f(S[j][2] - mn2);
            S[j][3] = exp2f(S[j][3] - mn2);
            sm1 += S[j][0] + S[j][1];
            sm2 += S[j][2] + S[j][3];
        }
        sm1 += __shfl_xor_sync(0xffffffffu, sm1, 1);
        sm1 += __shfl_xor_sync(0xffffffffu, sm1, 2);
        sm2 += __shfl_xor_sync(0xffffffffu, sm2, 1);
        sm2 += __shfl_xor_sync(0xffffffffu, sm2, 2);
        l1 = l1 * al1 + sm1;
        l2 = l2 * al2 + sm2;
        m1 = mn1;
        m2 = mn2;
        #pragma unroll
        for (int j = 0; j < 8; j++) {
            O[j][0] *= al1; O[j][1] *= al1;
            O[j][2] *= al2; O[j][3] *= al2;
        }

        unsigned pa[4][4];
        #pragma unroll
        for (int kc = 0; kc < 4; kc++) {
            pa[kc][0] = pack_h2(S[2 * kc][0],     S[2 * kc][1]);
            pa[kc][1] = pack_h2(S[2 * kc][2],     S[2 * kc][3]);
            pa[kc][2] = pack_h2(S[2 * kc + 1][0], S[2 * kc + 1][1]);
            pa[kc][3] = pack_h2(S[2 * kc + 1][2], S[2 * kc + 1][3]);
        }

        #pragma unroll
        for (int dg = 0; dg < 4; dg++) {
            #pragma unroll
            for (int tc = 0; tc < 4; tc++) {
                int vrow = tc * 16 + ((lg & 1) << 3) + lr;
                int vch  = dg * 2 + (lg >> 1);
                unsigned v0, v1, v2, v3;
                LDSM4T(v0, v1, v2, v3, curV + vrow * 128 + ((vch ^ (vrow & 7)) << 4));
                MMA168(O[dg * 2][0], O[dg * 2][1], O[dg * 2][2], O[dg * 2][3],
                       pa[tc][0], pa[tc][1], pa[tc][2], pa[tc][3], v0, v1);
                MMA168(O[dg * 2 + 1][0], O[dg * 2 + 1][1], O[dg * 2 + 1][2], O[dg * 2 + 1][3],
                       pa[tc][0], pa[tc][1], pa[tc][2], pa[tc][3], v2, v3);
            }
        }

        if (kt + 1 < nkv) {
            CPWAIT0();
            __syncthreads();
        }
    }

    float inv1 = 1.0f / l1;
    float inv2 = 1.0f / l2;
    size_t base1 = ((size_t)bb * SEQ + grow1) * 512 + hh * 64;
    size_t base2 = ((size_t)bb * SEQ + grow2) * 512 + hh * 64;
    #pragma unroll
    for (int j = 0; j < 8; j++) {
        int col = j * 8 + (lane & 3) * 2;
        *reinterpret_cast<__half2*>(&ctx[base1 + col]) =
            __floats2half2_rn(O[j][0] * inv1, O[j][1] * inv1);
        *reinterpret_cast<__half2*>(&ctx[base2 + col]) =
            __floats2half2_rn(O[j][2] * inv2, O[j][3] * inv2);
    }
}

extern "C" void kernel_launch(void* const* d_in, const int* in_sizes, int n_in,
                              void* d_out, int out_size)
{
    const float* src      = (const float*)d_in[0];
    const float* ln_w     = (const float*)d_in[1];
    const float* ln_b     = (const float*)d_in[2];
    const float* wqkv_w   = (const float*)d_in[3];
    const float* wqkv_b   = (const float*)d_in[4];
    const float* out_w    = (const float*)d_in[5];
    const float* out_b    = (const float*)d_in[6];
    const float* ffn_ln_w = (const float*)d_in[7];
    const float* ffn_ln_b = (const float*)d_in[8];
    const float* ff1_w    = (const float*)d_in[9];
    const float* ff1_b    = (const float*)d_in[10];
    const float* ff2_w    = (const float*)d_in[11];
    const float* ff2_b    = (const float*)d_in[12];
    float* out = (float*)d_out;

    __half *xln, *Q, *K, *V, *ctx, *hid, *wqkvh, *outwh, *ff1h, *ff2h;
    float *src2;
    float2* tab;
    cudaGetSymbolAddress((void**)&xln,   g_xln_h);
    cudaGetSymbolAddress((void**)&Q,     g_Qh);
    cudaGetSymbolAddress((void**)&K,     g_Kh);
    cudaGetSymbolAddress((void**)&V,     g_Vh);
    cudaGetSymbolAddress((void**)&ctx,   g_ctx_h);
    cudaGetSymbolAddress((void**)&src2,  g_src2);
    cudaGetSymbolAddress((void**)&hid,   g_hid_h);
    cudaGetSymbolAddress((void**)&tab,   g_rope);
    cudaGetSymbolAddress((void**)&wqkvh, g_wqkv_h);
    cudaGetSymbolAddress((void**)&outwh, g_outw_h);
    cudaGetSymbolAddress((void**)&ff1h,  g_ff1_h);
    cudaGetSymbolAddress((void**)&ff2h,  g_ff2_h);

    cudaFuncSetAttribute(gemm_mma<false, false, 2>,
                         cudaFuncAttributeMaxDynamicSharedMemorySize, GEMM_SMEM);
    cudaFuncSetAttribute(gemm_mma<false, true, 0>,
                         cudaFuncAttributeMaxDynamicSharedMemorySize, GEMM_SMEM);
    cudaFuncSetAttribute(gemm_mma<true, false, 1>,
                         cudaFuncAttributeMaxDynamicSharedMemorySize, GEMM_SMEM);
    cudaFuncSetAttribute(flash_mma,
                         cudaFuncAttributeMaxDynamicSharedMemorySize, FL_SMEM);

    int n4_total = N4_QKV + N4_OUT + N4_FF1 + N4_FF2;
    f2h_all<<<(n4_total + 255) / 256, 256>>>(wqkv_w, out_w, ff1_w, ff2_w,
                                             wqkvh, outwh, ff1h, ff2h);
    rope_tab_kernel<<<(SEQ * 32) / 256, 256>>>(tab);
    ln_kernel<<<ROWS, 128>>>(src, ln_w, ln_b, xln);

    // QKV projection with fused rope + split
    gemm_mma<false, false, 2><<<dim3(12, 64), 256, GEMM_SMEM>>>(
        xln, wqkvh, wqkv_b, nullptr, nullptr, nullptr, Q, K, V, tab,
        ROWS, 3 * D_MODEL, D_MODEL);

    flash_mma<<<dim3(SEQ / 128, BH), 256, FL_SMEM>>>(Q, K, V, ctx);

    gemm_mma<false, true, 0><<<dim3(4, 64), 256, GEMM_SMEM>>>(
        ctx, outwh, out_b, src, src2, nullptr, nullptr, nullptr, nullptr, nullptr,
        ROWS, D_MODEL, D_MODEL);

    ln_kernel<<<ROWS, 128>>>(src2, ffn_ln_w, ffn_ln_b, xln);

    gemm_mma<true, false, 1><<<dim3(16, 64), 256, GEMM_SMEM>>>(
        xln, ff1h, ff1_b, nullptr, nullptr, hid, nullptr, nullptr, nullptr, nullptr,
        ROWS, D_FF, D_MODEL);

    gemm_mma<false, true, 0><<<dim3(4, 64), 256, GEMM_SMEM>>>(
        hid, ff2h, ff2_b, src2, out, nullptr, nullptr, nullptr, nullptr, nullptr,
        ROWS, D_MODEL, D_FF);
}

// round 15
// speedup vs baseline: 1.1315x; 1.0157x over previous
#include <cuda_runtime.h>
#include <cuda_fp16.h>
#include <math.h>

#define D_MODEL 512
#define N_HEADS 8
#define HEAD_DIM 64
#define D_FF 2048
#define SEQ 4096
#define BATCH 2
#define ROWS (BATCH*SEQ)
#define BH (BATCH*N_HEADS)

// scratch buffers (no allocation allowed)
__device__ __half  g_xln_h [ROWS*D_MODEL];
__device__ __half  g_Qh    [BH*SEQ*HEAD_DIM];
__device__ __half  g_Kh    [BH*SEQ*HEAD_DIM];
__device__ __half  g_Vh    [BH*SEQ*HEAD_DIM];
__device__ __half  g_ctx_h [ROWS*D_MODEL];
__device__ float   g_src2  [ROWS*D_MODEL];
__device__ __half  g_hid_h [ROWS*D_FF];
__device__ float2  g_rope  [SEQ*32];
__device__ __half  g_wqkv_h[3*D_MODEL*D_MODEL];
__device__ __half  g_outw_h[D_MODEL*D_MODEL];
__device__ __half  g_ff1_h [D_FF*D_MODEL];
__device__ __half  g_ff2_h [D_MODEL*D_FF];

// asm macros
#define CP16(dst, src) \
    asm volatile("cp.async.cg.shared.global [%0], [%1], 16;" :: "r"(dst), "l"(src))
#define CPCOMMIT() asm volatile("cp.async.commit_group;")
#define CPWAIT0()  asm volatile("cp.async.wait_group 0;")
#define CPWAIT1()  asm volatile("cp.async.wait_group 1;")
#define LDSM4(r0, r1, r2, r3, addr) \
    asm volatile("ldmatrix.sync.aligned.m8n8.x4.shared.b16 {%0,%1,%2,%3}, [%4];" \
                 : "=r"(r0), "=r"(r1), "=r"(r2), "=r"(r3) : "r"(addr))
#define LDSM4T(r0, r1, r2, r3, addr) \
    asm volatile("ldmatrix.sync.aligned.m8n8.x4.trans.shared.b16 {%0,%1,%2,%3}, [%4];" \
                 : "=r"(r0), "=r"(r1), "=r"(r2), "=r"(r3) : "r"(addr))
#define MMA168(c0, c1, c2, c3, a0, a1, a2, a3, b0, b1) \
    asm volatile("mma.sync.aligned.m16n8k16.row.col.f32.f16.f16.f32 " \
                 "{%0,%1,%2,%3},{%4,%5,%6,%7},{%8,%9},{%0,%1,%2,%3};" \
                 : "+f"(c0), "+f"(c1), "+f"(c2), "+f"(c3) \
                 : "r"(a0), "r"(a1), "r"(a2), "r"(a3), "r"(b0), "r"(b1))

__device__ __forceinline__ unsigned smem_u32(const void* p)
{
    return (unsigned)__cvta_generic_to_shared(p);
}
__device__ __forceinline__ unsigned pack_h2(float a, float b)
{
    __half2 h = __floats2half2_rn(a, b);
    return *reinterpret_cast<unsigned*>(&h);
}

// float4 counts for weight conversion
#define N4_QKV (3*D_MODEL*D_MODEL/4)
#define N4_OUT (D_MODEL*D_MODEL/4)
#define N4_FF1 (D_FF*D_MODEL/4)
#define N4_FF2 (D_MODEL*D_FF/4)
#define N4_TOT (N4_QKV + N4_OUT + N4_FF1 + N4_FF2)

// fused glue kernel: LN1 (2 rows/block) + weights f2h + rope table, one launch
#define GLUE_LNB  (ROWS/2)          /* 4096 */
#define GLUE_F2HB (N4_TOT/256)      /* 3072 */
#define GLUE_ROPEB (SEQ*32/256)     /* 512 */
#define GLUE_BLOCKS (GLUE_LNB + GLUE_F2HB + GLUE_ROPEB)

__global__ void __launch_bounds__(256) glue_kernel(const float* __restrict__ x,
                                                   const float* __restrict__ lnw,
                                                   const float* __restrict__ lnb,
                                                   __half* __restrict__ y,
                                                   const float* __restrict__ w0,
                                                   const float* __restrict__ w1,
                                                   const float* __restrict__ w2,
                                                   const float* __restrict__ w3,
                                                   __half* __restrict__ o0,
                                                   __half* __restrict__ o1,
                                                   __half* __restrict__ o2,
                                                   __half* __restrict__ o3,
                                                   float2* __restrict__ tab)
{
    int blk = blockIdx.x;
    int t = threadIdx.x;

    if (blk < GLUE_LNB) {
        // LayerNorm: two rows per block, 128 threads each
        int half = t >> 7;
        int tl = t & 127;
        int row = blk * 2 + half;
        const float4* xr = reinterpret_cast<const float4*>(x) + (size_t)row * 128;
        float4 v = xr[tl];
        float s  = v.x + v.y + v.z + v.w;
        float ss = v.x*v.x + v.y*v.y + v.z*v.z + v.w*v.w;
        #pragma unroll
        for (int off = 16; off >= 1; off >>= 1) {
            s  += __shfl_xor_sync(0xffffffffu, s,  off);
            ss += __shfl_xor_sync(0xffffffffu, ss, off);
        }
        __shared__ float rs[8], rss[8];
        int wid = t >> 5;
        if ((t & 31) == 0) { rs[wid] = s; rss[wid] = ss; }
        __syncthreads();
        int base = half * 4;
        s  = rs[base] + rs[base+1] + rs[base+2] + rs[base+3];
        ss = rss[base] + rss[base+1] + rss[base+2] + rss[base+3];
        float mu  = s * (1.0f / 512.0f);
        float var = ss * (1.0f / 512.0f) - mu * mu;
        float r   = rsqrtf(var + 1e-5f);
        float4 w4 = reinterpret_cast<const float4*>(lnw)[tl];
        float4 b4 = reinterpret_cast<const float4*>(lnb)[tl];
        __half2* yr = reinterpret_cast<__half2*>(y) + (size_t)row * 256;
        yr[tl * 2 + 0] = __floats2half2_rn((v.x - mu) * r * w4.x + b4.x,
                                           (v.y - mu) * r * w4.y + b4.y);
        yr[tl * 2 + 1] = __floats2half2_rn((v.z - mu) * r * w4.z + b4.z,
                                           (v.w - mu) * r * w4.w + b4.w);
    } else if (blk < GLUE_LNB + GLUE_F2HB) {
        int i = (blk - GLUE_LNB) * 256 + t;
        const float* in;
        __half* out;
        int k;
        if (i < N4_QKV) {
            in = w0; out = o0; k = i;
        } else if (i < N4_QKV + N4_OUT) {
            in = w1; out = o1; k = i - N4_QKV;
        } else if (i < N4_QKV + N4_OUT + N4_FF1) {
            in = w2; out = o2; k = i - N4_QKV - N4_OUT;
        } else {
            in = w3; out = o3; k = i - N4_QKV - N4_OUT - N4_FF1;
        }
        float4 v = reinterpret_cast<const float4*>(in)[k];
        reinterpret_cast<__half2*>(out)[k * 2 + 0] = __floats2half2_rn(v.x, v.y);
        reinterpret_cast<__half2*>(out)[k * 2 + 1] = __floats2half2_rn(v.z, v.w);
    } else {
        int idx = (blk - GLUE_LNB - GLUE_F2HB) * 256 + t;
        int s = idx >> 5;
        int i = idx & 31;
        double freq = 1.0 / pow(10000.0, (double)i / 32.0);
        float ang = (float)((double)s * freq);
        tab[idx] = make_float2(cosf(ang), sinf(ang));
    }
}

// LayerNorm standalone (for LN2), one block per row of 512, half output
__global__ void __launch_bounds__(128) ln_kernel(const float* __restrict__ x,
                                                 const float* __restrict__ w,
                                                 const float* __restrict__ b,
                                                 __half* __restrict__ y)
{
    int row = blockIdx.x;
    int t = threadIdx.x;
    const float4* xr = reinterpret_cast<const float4*>(x) + (size_t)row * 128;
    float4 v = xr[t];
    float s  = v.x + v.y + v.z + v.w;
    float ss = v.x*v.x + v.y*v.y + v.z*v.z + v.w*v.w;
    #pragma unroll
    for (int off = 16; off >= 1; off >>= 1) {
        s  += __shfl_xor_sync(0xffffffffu, s,  off);
        ss += __shfl_xor_sync(0xffffffffu, ss, off);
    }
    __shared__ float rs[4], rss[4];
    int wid = t >> 5;
    if ((t & 31) == 0) { rs[wid] = s; rss[wid] = ss; }
    __syncthreads();
    s  = rs[0] + rs[1] + rs[2] + rs[3];
    ss = rss[0] + rss[1] + rss[2] + rss[3];
    float mu  = s * (1.0f / 512.0f);
    float var = ss * (1.0f / 512.0f) - mu * mu;
    float r   = rsqrtf(var + 1e-5f);
    float4 w4 = reinterpret_cast<const float4*>(w)[t];
    float4 b4 = reinterpret_cast<const float4*>(b)[t];
    __half2* yr = reinterpret_cast<__half2*>(y) + (size_t)row * 256;
    yr[t * 2 + 0] = __floats2half2_rn((v.x - mu) * r * w4.x + b4.x,
                                      (v.y - mu) * r * w4.y + b4.y);
    yr[t * 2 + 1] = __floats2half2_rn((v.z - mu) * r * w4.z + b4.z,
                                      (v.w - mu) * r * w4.w + b4.w);
}

// raw mma NT GEMM (round-13 proven config): 128x128 tile, BK=64, 3-stage ring,
// 8 warps in 4x2, warp tile 32x64.
// OUTM: 0 = fp32 C (+resid), 1 = half Ch, 2 = fused rope split to Q/K/V
// (Q pre-scaled by 0.125*log2(e) for exp2-domain softmax in flash)
#define GSTAGE 16384u
#define GEMM_SMEM (6 * 16384)
#define QSCALE 0.18033688f

template<bool RELU, bool RESID, int OUTM>
__global__ void __launch_bounds__(256) gemm_mma(const __half* __restrict__ A,
                                                const __half* __restrict__ W,
                                                const float* __restrict__ bias,
                                                const float* __restrict__ resid,
                                                float* __restrict__ C,
                                                __half* __restrict__ Ch,
                                                __half* __restrict__ Qp,
                                                __half* __restrict__ Kp,
                                                __half* __restrict__ Vp,
                                                const float2* __restrict__ tab,
                                                int M, int N, int K)
{
    extern __shared__ __half smg[];
    unsigned aA = smem_u32(smg);
    unsigned aB = aA + 3 * GSTAGE;
    int tid = threadIdx.x;
    int lane = tid & 31;
    int wid = tid >> 5;
    int wr = wid >> 1;
    int wc = wid & 1;
    int lr = lane & 7;
    int lg = lane >> 3;
    int bm = blockIdx.y * 128;
    int bn = blockIdx.x * 128;
    int nK = K >> 6;

    const __half* Ag = A + (size_t)bm * K;
    const __half* Wg = W + (size_t)bn * K;

    float acc[2][8][4];
    #pragma unroll
    for (int i = 0; i < 2; i++) {
        #pragma unroll
        for (int j = 0; j < 8; j++) {
            acc[i][j][0] = 0.0f; acc[i][j][1] = 0.0f;
            acc[i][j][2] = 0.0f; acc[i][j][3] = 0.0f;
        }
    }

    // prologue: stages 0 and 1
    for (int st = 0; st < 2; st++) {
        unsigned dA = aA + (unsigned)st * GSTAGE;
        unsigned dB = aB + (unsigned)st * GSTAGE;
        int k0 = st * 64;
        #pragma unroll
        for (int i2 = 0; i2 < 4; i2++) {
            int idx = tid + i2 * 256;
            int rr = idx >> 3;
            int cc = idx & 7;
            CP16(dA + rr * 128 + ((cc ^ (rr & 7)) << 4), Ag + (size_t)rr * K + k0 + cc * 8);
            CP16(dB + rr * 128 + ((cc ^ (rr & 7)) << 4), Wg + (size_t)rr * K + k0 + cc * 8);
        }
        CPCOMMIT();
    }

    for (int kt = 0; kt < nK; kt++) {
        if (kt < nK - 1) {
            CPWAIT1();
        } else {
            CPWAIT0();
        }
        __syncthreads();
        if (kt + 2 < nK) {
            int st = (kt + 2) % 3;
            unsigned dA = aA + (unsigned)st * GSTAGE;
            unsigned dB = aB + (unsigned)st * GSTAGE;
            int k0 = (kt + 2) * 64;
            #pragma unroll
            for (int i2 = 0; i2 < 4; i2++) {
                int idx = tid + i2 * 256;
                int rr = idx >> 3;
                int cc = idx & 7;
                CP16(dA + rr * 128 + ((cc ^ (rr & 7)) << 4), Ag + (size_t)rr * K + k0 + cc * 8);
                CP16(dB + rr * 128 + ((cc ^ (rr & 7)) << 4), Wg + (size_t)rr * K + k0 + cc * 8);
            }
            CPCOMMIT();
        }
        unsigned cA = aA + (unsigned)(kt % 3) * GSTAGE;
        unsigned cB = aB + (unsigned)(kt % 3) * GSTAGE;
        #pragma unroll
        for (int kc = 0; kc < 4; kc++) {
            unsigned af0[4], af1[4];
            int arow = wr * 32 + ((lg & 1) << 3) + lr;
            int ach = kc * 2 + (lg >> 1);
            LDSM4(af0[0], af0[1], af0[2], af0[3],
                  cA + arow * 128 + ((ach ^ (arow & 7)) << 4));
            int arow2 = arow + 16;
            LDSM4(af1[0], af1[1], af1[2], af1[3],
                  cA + arow2 * 128 + ((ach ^ (arow2 & 7)) << 4));
            #pragma unroll
            for (int jj = 0; jj < 4; jj++) {
                int brow = wc * 64 + jj * 16 + ((lg >> 1) << 3) + lr;
                int bch = kc * 2 + (lg & 1);
                unsigned b0, b1, b2, b3;
                LDSM4(b0, b1, b2, b3, cB + brow * 128 + ((bch ^ (brow & 7)) << 4));
                MMA168(acc[0][2*jj][0], acc[0][2*jj][1], acc[0][2*jj][2], acc[0][2*jj][3],
                       af0[0], af0[1], af0[2], af0[3], b0, b1);
                MMA168(acc[0][2*jj+1][0], acc[0][2*jj+1][1], acc[0][2*jj+1][2], acc[0][2*jj+1][3],
                       af0[0], af0[1], af0[2], af0[3], b2, b3);
                MMA168(acc[1][2*jj][0], acc[1][2*jj][1], acc[1][2*jj][2], acc[1][2*jj][3],
                       af1[0], af1[1], af1[2], af1[3], b0, b1);
                MMA168(acc[1][2*jj+1][0], acc[1][2*jj+1][1], acc[1][2*jj+1][2], acc[1][2*jj+1][3],
                       af1[0], af1[1], af1[2], af1[3], b2, b3);
            }
        }
    }

    // epilogue straight from registers
    #pragma unroll
    for (int i = 0; i < 2; i++) {
        int r1 = bm + wr * 32 + i * 16 + (lane >> 2);
        int r2 = r1 + 8;
        #pragma unroll
        for (int j = 0; j < 8; j++) {
            int gc = bn + wc * 64 + j * 8 + (lane & 3) * 2;
            float2 bb = *reinterpret_cast<const float2*>(&bias[gc]);
            float c0 = acc[i][j][0] + bb.x;
            float c1 = acc[i][j][1] + bb.y;
            float c2 = acc[i][j][2] + bb.x;
            float c3 = acc[i][j][3] + bb.y;
            if (RELU) {
                c0 = fmaxf(c0, 0.0f); c1 = fmaxf(c1, 0.0f);
                c2 = fmaxf(c2, 0.0f); c3 = fmaxf(c3, 0.0f);
            }
            if (OUTM == 0) {
                if (RESID) {
                    float2 rv1 = *reinterpret_cast<const float2*>(&resid[(size_t)r1 * N + gc]);
                    float2 rv2 = *reinterpret_cast<const float2*>(&resid[(size_t)r2 * N + gc]);
                    c0 += rv1.x; c1 += rv1.y;
                    c2 += rv2.x; c3 += rv2.y;
                }
                *reinterpret_cast<float2*>(&C[(size_t)r1 * N + gc]) = make_float2(c0, c1);
                *reinterpret_cast<float2*>(&C[(size_t)r2 * N + gc]) = make_float2(c2, c3);
            } else if (OUTM == 1) {
                *reinterpret_cast<__half2*>(&Ch[(size_t)r1 * N + gc]) = __floats2half2_rn(c0, c1);
                *reinterpret_cast<__half2*>(&Ch[(size_t)r2 * N + gc]) = __floats2half2_rn(c2, c3);
            } else {
                int type = gc >> 9;
                int head = (gc >> 6) & 7;
                int d    = gc & 63;
                int s1 = r1 & (SEQ - 1);
                int s2 = r2 & (SEQ - 1);
                int bi1 = r1 >> 12;
                int bi2 = r2 >> 12;
                size_t oo1 = ((((size_t)bi1 * 8 + head) * SEQ) + s1) * 64 + d;
                size_t oo2 = ((((size_t)bi2 * 8 + head) * SEQ) + s2) * 64 + d;
                if (type == 2) {
                    *reinterpret_cast<__half2*>(&Vp[oo1]) = __floats2half2_rn(c0, c1);
                    *reinterpret_cast<__half2*>(&Vp[oo2]) = __floats2half2_rn(c2, c3);
                } else {
                    float2 cs1 = tab[s1 * 32 + (d >> 1)];
                    float2 cs2 = tab[s2 * 32 + (d >> 1)];
                    float x1 = c0 * cs1.x - c1 * cs1.y;
                    float y1 = c0 * cs1.y + c1 * cs1.x;
                    float x2 = c2 * cs2.x - c3 * cs2.y;
                    float y2 = c2 * cs2.y + c3 * cs2.x;
                    if (type == 0) {
                        *reinterpret_cast<__half2*>(&Qp[oo1]) =
                            __floats2half2_rn(x1 * QSCALE, y1 * QSCALE);
                        *reinterpret_cast<__half2*>(&Qp[oo2]) =
                            __floats2half2_rn(x2 * QSCALE, y2 * QSCALE);
                    } else {
                        *reinterpret_cast<__half2*>(&Kp[oo1]) = __floats2half2_rn(x1, y1);
                        *reinterpret_cast<__half2*>(&Kp[oo2]) = __floats2half2_rn(x2, y2);
                    }
                }
            }
        }
    }
}

// register-resident causal flash attention, Q tile 128 rows, 256 threads (8 warps),
// KV tile 64, exp2-domain softmax (Q pre-scaled by 0.125*log2e).
#define FL_SMEM 49152

__global__ void __launch_bounds__(256) flash_mma(const __half* __restrict__ Qg,
                                                 const __half* __restrict__ Kg,
                                                 const __half* __restrict__ Vg,
                                                 __half* __restrict__ ctx)
{
    extern __shared__ char fsm[];
    unsigned aQ  = smem_u32(fsm);
    unsigned aK0 = aQ + 16384;
    unsigned aK1 = aQ + 24576;
    unsigned aV0 = aQ + 32768;
    unsigned aV1 = aQ + 40960;

    int qt = (int)gridDim.x - 1 - blockIdx.x;
    int bh = blockIdx.y;
    int bb = bh >> 3;
    int hh = bh & 7;
    const __half* Qb = Qg + ((size_t)bh * SEQ + qt * 128) * 64;
    const __half* Kb = Kg + (size_t)bh * SEQ * 64;
    const __half* Vb = Vg + (size_t)bh * SEQ * 64;

    int tid = threadIdx.x;
    int lane = tid & 31;
    int wq = tid >> 5;
    int lr = lane & 7;
    int lg = lane >> 3;

    {
        #pragma unroll
        for (int i = 0; i < 4; i++) {
            int idx = tid + i * 256;
            int r = idx >> 3;
            int c = idx & 7;
            CP16(aQ + r * 128 + ((c ^ (r & 7)) << 4), Qb + (size_t)r * 64 + c * 8);
        }
        #pragma unroll
        for (int i = 0; i < 2; i++) {
            int idx = tid + i * 256;
            int r = idx >> 3;
            int c = idx & 7;
            CP16(aK0 + r * 128 + ((c ^ (r & 7)) << 4), Kb + (size_t)r * 64 + c * 8);
            CP16(aV0 + r * 128 + ((c ^ (r & 7)) << 4), Vb + (size_t)r * 64 + c * 8);
        }
    }
    CPCOMMIT();
    CPWAIT0();
    __syncthreads();

    unsigned qa[4][4];
    #pragma unroll
    for (int kc = 0; kc < 4; kc++) {
        int qrow = wq * 16 + ((lg & 1) << 3) + lr;
        int qch  = kc * 2 + (lg >> 1);
        LDSM4(qa[kc][0], qa[kc][1], qa[kc][2], qa[kc][3],
              aQ + qrow * 128 + ((qch ^ (qrow & 7)) << 4));
    }

    float O[8][4];
    #pragma unroll
    for (int j = 0; j < 8; j++) {
        O[j][0] = 0.0f; O[j][1] = 0.0f; O[j][2] = 0.0f; O[j][3] = 0.0f;
    }
    float m1 = -1e30f;
    float m2 = -1e30f;
    float l1 = 0.0f;
    float l2 = 0.0f;

    int grow1 = qt * 128 + wq * 16 + (lane >> 2);
    int grow2 = grow1 + 8;
    int nkv = 2 * qt + 2;

    for (int kt = 0; kt < nkv; ++kt) {
        unsigned curK = (kt & 1) ? aK1 : aK0;
        unsigned curV = (kt & 1) ? aV1 : aV0;
        unsigned nxtK = (kt & 1) ? aK0 : aK1;
        unsigned nxtV = (kt & 1) ? aV0 : aV1;
        if (kt + 1 < nkv) {
            const __half* Kn = Kb + (size_t)(kt + 1) * 4096;
            const __half* Vn = Vb + (size_t)(kt + 1) * 4096;
            #pragma unroll
            for (int i = 0; i < 2; i++) {
                int idx = tid + i * 256;
                int r = idx >> 3;
                int c = idx & 7;
                CP16(nxtK + r * 128 + ((c ^ (r & 7)) << 4), Kn + (size_t)r * 64 + c * 8);
                CP16(nxtV + r * 128 + ((c ^ (r & 7)) << 4), Vn + (size_t)r * 64 + c * 8);
            }
            CPCOMMIT();
        }

        float S[8][4];
        #pragma unroll
        for (int j = 0; j < 8; j++) {
            S[j][0] = 0.0f; S[j][1] = 0.0f; S[j][2] = 0.0f; S[j][3] = 0.0f;
        }
        #pragma unroll
        for (int ng = 0; ng < 4; ng++) {
            #pragma unroll
            for (int kc = 0; kc < 4; kc++) {
                int krow = ng * 16 + ((lg >> 1) << 3) + lr;
                int kch  = kc * 2 + (lg & 1);
                unsigned b0, b1, b2, b3;
                LDSM4(b0, b1, b2, b3, curK + krow * 128 + ((kch ^ (krow & 7)) << 4));
                MMA168(S[ng * 2][0], S[ng * 2][1], S[ng * 2][2], S[ng * 2][3],
                       qa[kc][0], qa[kc][1], qa[kc][2], qa[kc][3], b0, b1);
                MMA168(S[ng * 2 + 1][0], S[ng * 2 + 1][1], S[ng * 2 + 1][2], S[ng * 2 + 1][3],
                       qa[kc][0], qa[kc][1], qa[kc][2], qa[kc][3], b2, b3);
            }
        }

        if (kt >= 2 * qt) {
            #pragma unroll
            for (int j = 0; j < 8; j++) {
                int col = kt * 64 + j * 8 + (lane & 3) * 2;
                if (col     > grow1) S[j][0] = -1e30f;
                if (col + 1 > grow1) S[j][1] = -1e30f;
                if (col     > grow2) S[j][2] = -1e30f;
                if (col + 1 > grow2) S[j][3] = -1e30f;
            }
        }

        float mx1 = -1e30f;
        float mx2 = -1e30f;
        #pragma unroll
        for (int j = 0; j < 8; j++) {
            mx1 = fmaxf(mx1, fmaxf(S[j][0], S[j][1]));
            mx2 = fmaxf(mx2, fmaxf(S[j][2], S[j][3]));
        }
        mx1 = fmaxf(mx1, __shfl_xor_sync(0xffffffffu, mx1, 1));
        mx1 = fmaxf(mx1, __shfl_xor_sync(0xffffffffu, mx1, 2));
        mx2 = fmaxf(mx2, __shfl_xor_sync(0xffffffffu, mx2, 1));
        mx2 = fmaxf(mx2, __shfl_xor_sync(0xffffffffu, mx2, 2));
        float mn1 = fmaxf(m1, mx1);
        float mn2 = fmaxf(m2, mx2);
        float al1 = exp2f(m1 - mn1);
        float al2 = exp2f(m2 - mn2);
        float sm1 = 0.0f;
        float sm2 = 0.0f;
        #pragma unroll
        for (int j = 0; j < 8; j++) {
            S[j][0] = exp2f(S[j][0] - mn1);
            S[j][1] = exp2f(S[j][1] - mn1);
            S[j][2] = exp2f(S[j][2] - mn2);
            S[j][3] = exp2f(S[j][3] - mn2);
            sm1 += S[j][0] + S[j][1];
            sm2 += S[j][2] + S[j][3];
        }
        sm1 += __shfl_xor_sync(0xffffffffu, sm1, 1);
        sm1 += __shfl_xor_sync(0xffffffffu, sm1, 2);
        sm2 += __shfl_xor_sync(0xffffffffu, sm2, 1);
        sm2 += __shfl_xor_sync(0xffffffffu, sm2, 2);
        l1 = l1 * al1 + sm1;
        l2 = l2 * al2 + sm2;
        m1 = mn1;
        m2 = mn2;
        #pragma unroll
        for (int j = 0; j < 8; j++) {
            O[j][0] *= al1; O[j][1] *= al1;
            O[j][2] *= al2; O[j][3] *= al2;
        }

        unsigned pa[4][4];
        #pragma unroll
        for (int kc = 0; kc < 4; kc++) {
            pa[kc][0] = pack_h2(S[2 * kc][0],     S[2 * kc][1]);
            pa[kc][1] = pack_h2(S[2 * kc][2],     S[2 * kc][3]);
            pa[kc][2] = pack_h2(S[2 * kc + 1][0], S[2 * kc + 1][1]);
            pa[kc][3] = pack_h2(S[2 * kc + 1][2], S[2 * kc + 1][3]);
        }

        #pragma unroll
        for (int dg = 0; dg < 4; dg++) {
            #pragma unroll
            for (int tc = 0; tc < 4; tc++) {
                int vrow = tc * 16 + ((lg & 1) << 3) + lr;
                int vch  = dg * 2 + (lg >> 1);
                unsigned v0, v1, v2, v3;
                LDSM4T(v0, v1, v2, v3, curV + vrow * 128 + ((vch ^ (vrow & 7)) << 4));
                MMA168(O[dg * 2][0], O[dg * 2][1], O[dg * 2][2], O[dg * 2][3],
                       pa[tc][0], pa[tc][1], pa[tc][2], pa[tc][3], v0, v1);
                MMA168(O[dg * 2 + 1][0], O[dg * 2 + 1][1], O[dg * 2 + 1][2], O[dg * 2 + 1][3],
                       pa[tc][0], pa[tc][1], pa[tc][2], pa[tc][3], v2, v3);
            }
        }

        if (kt + 1 < nkv) {
            CPWAIT0();
            __syncthreads();
        }
    }

    float inv1 = 1.0f / l1;
    float inv2 = 1.0f / l2;
    size_t base1 = ((size_t)bb * SEQ + grow1) * 512 + hh * 64;
    size_t base2 = ((size_t)bb * SEQ + grow2) * 512 + hh * 64;
    #pragma unroll
    for (int j = 0; j < 8; j++) {
        int col = j * 8 + (lane & 3) * 2;
        *reinterpret_cast<__half2*>(&ctx[base1 + col]) =
            __floats2half2_rn(O[j][0] * inv1, O[j][1] * inv1);
        *reinterpret_cast<__half2*>(&ctx[base2 + col]) =
            __floats2half2_rn(O[j][2] * inv2, O[j][3] * inv2);
    }
}

extern "C" void kernel_launch(void* const* d_in, const int* in_sizes, int n_in,
                              void* d_out, int out_size)
{
    const float* src      = (const float*)d_in[0];
    const float* ln_w     = (const float*)d_in[1];
    const float* ln_b     = (const float*)d_in[2];
    const float* wqkv_w   = (const float*)d_in[3];
    const float* wqkv_b   = (const float*)d_in[4];
    const float* out_w    = (const float*)d_in[5];
    const float* out_b    = (const float*)d_in[6];
    const float* ffn_ln_w = (const float*)d_in[7];
    const float* ffn_ln_b = (const float*)d_in[8];
    const float* ff1_w    = (const float*)d_in[9];
    const float* ff1_b    = (const float*)d_in[10];
    const float* ff2_w    = (const float*)d_in[11];
    const float* ff2_b    = (const float*)d_in[12];
    float* out = (float*)d_out;

    __half *xln, *Q, *K, *V, *ctx, *hid, *wqkvh, *outwh, *ff1h, *ff2h;
    float *src2;
    float2* tab;
    cudaGetSymbolAddress((void**)&xln,   g_xln_h);
    cudaGetSymbolAddress((void**)&Q,     g_Qh);
    cudaGetSymbolAddress((void**)&K,     g_Kh);
    cudaGetSymbolAddress((void**)&V,     g_Vh);
    cudaGetSymbolAddress((void**)&ctx,   g_ctx_h);
    cudaGetSymbolAddress((void**)&src2,  g_src2);
    cudaGetSymbolAddress((void**)&hid,   g_hid_h);
    cudaGetSymbolAddress((void**)&tab,   g_rope);
    cudaGetSymbolAddress((void**)&wqkvh, g_wqkv_h);
    cudaGetSymbolAddress((void**)&outwh, g_outw_h);
    cudaGetSymbolAddress((void**)&ff1h,  g_ff1_h);
    cudaGetSymbolAddress((void**)&ff2h,  g_ff2_h);

    cudaFuncSetAttribute(gemm_mma<false, false, 2>,
                         cudaFuncAttributeMaxDynamicSharedMemorySize, GEMM_SMEM);
    cudaFuncSetAttribute(gemm_mma<false, true, 0>,
                         cudaFuncAttributeMaxDynamicSharedMemorySize, GEMM_SMEM);
    cudaFuncSetAttribute(gemm_mma<true, false, 1>,
                         cudaFuncAttributeMaxDynamicSharedMemorySize, GEMM_SMEM);
    cudaFuncSetAttribute(flash_mma,
                         cudaFuncAttributeMaxDynamicSharedMemorySize, FL_SMEM);

    // fused prologue: LN1 + weight conversion + rope table in one launch
    glue_kernel<<<GLUE_BLOCKS, 256>>>(src, ln_w, ln_b, xln,
                                      wqkv_w, out_w, ff1_w, ff2_w,
                                      wqkvh, outwh, ff1h, ff2h, tab);

    // QKV projection with fused rope + split
    gemm_mma<false, false, 2><<<dim3(12, 64), 256, GEMM_SMEM>>>(
        xln, wqkvh, wqkv_b, nullptr, nullptr, nullptr, Q, K, V, tab,
        ROWS, 3 * D_MODEL, D_MODEL);

    flash_mma<<<dim3(SEQ / 128, BH), 256, FL_SMEM>>>(Q, K, V, ctx);

    gemm_mma<false, true, 0><<<dim3(4, 64), 256, GEMM_SMEM>>>(
        ctx, outwh, out_b, src, src2, nullptr, nullptr, nullptr, nullptr, nullptr,
        ROWS, D_MODEL, D_MODEL);

    ln_kernel<<<ROWS, 128>>>(src2, ffn_ln_w, ffn_ln_b, xln);

    gemm_mma<true, false, 1><<<dim3(16, 64), 256, GEMM_SMEM>>>(
        xln, ff1h, ff1_b, nullptr, nullptr, hid, nullptr, nullptr, nullptr, nullptr,
        ROWS, D_FF, D_MODEL);

    gemm_mma<false, true, 0><<<dim3(4, 64), 256, GEMM_SMEM>>>(
        hid, ff2h, ff2_b, src2, out, nullptr, nullptr, nullptr, nullptr, nullptr,
        ROWS, D_MODEL, D_FF);
}